// round 12
// baseline (speedup 1.0000x reference)
#include <cuda_runtime.h>
#include <cuda_bf16.h>
#include <math.h>

#define Bv 8
#define Sv 2048
#define Dv 320
#define NHv 5
#define HDv 64
#define FFv 864
#define NLv 6
#define NLOOPSv 8
#define TOK (Bv*Sv)
#define KSEL 1638
#define MPAD 1664
#define MSEL (Bv*MPAD)   // 13312

// ---------------- scratch ----------------
__device__ float g_x[TOK*Dv];
__device__ __nv_bfloat16 g_h[TOK*Dv];     // bf16 GEMM A input
__device__ float g_q[Bv*NHv*Sv*HDv];      // tf32 [B][H][S][HD]
__device__ float g_k[Bv*NHv*Sv*HDv];      // tf32 [B][H][S][HD]
__device__ __nv_bfloat16 g_v[Bv*NHv*Sv*HDv]; // bf16 TRANSPOSED [B][H][HD][S]
__device__ __nv_bfloat16 g_att[TOK*Dv];   // bf16 (WO GEMM A)
__device__ float g_probs[TOK];
__device__ int   g_sel[MSEL];
__device__ float g_wselc[MSEL];
__device__ __nv_bfloat16 g_g2[TOK*FFv];   // swiglu act bf16 (down GEMM A)

#define OFF_QKV  0
#define OFF_WO   1843200
#define OFF_GATE 2457600
#define OFF_UP   4116480
#define OFF_DOWN 5775360
#define TOTW     7434240
__device__ __nv_bfloat16 g_wt[TOTW];

__device__ __forceinline__ float to_tf32(float x){
    unsigned u; asm("cvt.rna.tf32.f32 %0, %1;" : "=r"(u) : "f"(x));
    return __uint_as_float(u);
}
__device__ __forceinline__ unsigned fbits(float x){ return __float_as_uint(x); }

#define MMA_TF32(acc, A0,A1,A2,A3, B0,B1)                                   \
    asm volatile(                                                           \
        "mma.sync.aligned.m16n8k8.row.col.f32.tf32.tf32.f32 "               \
        "{%0,%1,%2,%3},{%4,%5,%6,%7},{%8,%9},{%0,%1,%2,%3};\n"              \
        : "+f"(acc[0]),"+f"(acc[1]),"+f"(acc[2]),"+f"(acc[3])               \
        : "r"(A0),"r"(A1),"r"(A2),"r"(A3),"r"(B0),"r"(B1))

#define MMA_BF16(acc, A0,A1,A2,A3, B0,B1)                                   \
    asm volatile(                                                           \
        "mma.sync.aligned.m16n8k16.row.col.f32.bf16.bf16.f32 "              \
        "{%0,%1,%2,%3},{%4,%5,%6,%7},{%8,%9},{%0,%1,%2,%3};\n"              \
        : "+f"(acc[0]),"+f"(acc[1]),"+f"(acc[2]),"+f"(acc[3])               \
        : "r"(A0),"r"(A1),"r"(A2),"r"(A3),"r"(B0),"r"(B1))

#define LDSM4(r0,r1,r2,r3, addr)                                            \
    asm volatile("ldmatrix.sync.aligned.m8n8.x4.shared.b16 {%0,%1,%2,%3}, [%4];" \
        : "=r"(r0),"=r"(r1),"=r"(r2),"=r"(r3) : "r"(addr))

#define CPA(dst, src) asm volatile("cp.async.cg.shared.global [%0], [%1], 16;\n" :: "r"(dst), "l"(src))
#define CPAZ(dst, src, sz) asm volatile("cp.async.cg.shared.global [%0], [%1], 16, %2;\n" :: "r"(dst), "l"(src), "r"(sz))

// ---------------- conversions / embedding ----------------
__global__ void k_cvt(const float* __restrict__ in, __nv_bfloat16* __restrict__ out, int n){
    int i = blockIdx.x*256 + threadIdx.x;
    if (i < n) out[i] = __float2bfloat16(in[i]);
}

__global__ void k_embed(const int* __restrict__ ids, const int* __restrict__ iter,
                        const float* __restrict__ emb, const float* __restrict__ iter_emb) {
    int idx = blockIdx.x*256 + threadIdx.x;
    if (idx >= TOK*Dv) return;
    int t = idx / Dv, d = idx - t*Dv;
    float v = emb[(size_t)ids[t]*Dv + d];
    int it = iter[0];
    if (it < NLOOPSv) v += iter_emb[it*Dv + d];
    g_x[idx] = v;
}

__global__ void k_clearpad(){
    int i = threadIdx.x;
    if (i < Bv*(MPAD-KSEL)){
        int b = i/(MPAD-KSEL), j = i%(MPAD-KSEL);
        g_sel[b*MPAD + KSEL + j] = -1;
        g_wselc[b*MPAD + KSEL + j] = 0.f;
    }
}

// ---------------- rmsnorm (dense): writes bf16 (outb) or fp32 (outf) ----------------
__global__ void k_rmsnorm(const float* __restrict__ in, const float* __restrict__ w,
                          float* __restrict__ outf, __nv_bfloat16* __restrict__ outb) {
    int gw = (blockIdx.x*256 + threadIdx.x) >> 5;
    int lane = threadIdx.x & 31;
    if (gw >= TOK) return;
    const float* xr = in + (size_t)gw*Dv;
    float v[10]; float ss = 0.f;
    #pragma unroll
    for (int i=0;i<10;i++){ v[i] = xr[lane+32*i]; ss = fmaf(v[i],v[i],ss); }
    #pragma unroll
    for (int o=16;o;o>>=1) ss += __shfl_xor_sync(0xffffffffu, ss, o);
    float inv = rsqrtf(ss*(1.f/Dv) + 1e-6f);
    if (outb){
        __nv_bfloat16* orow = outb + (size_t)gw*Dv;
        #pragma unroll
        for (int i=0;i<10;i++) orow[lane+32*i] = __float2bfloat16(w[lane+32*i]*v[i]*inv);
    } else {
        float* orow = outf + (size_t)gw*Dv;
        #pragma unroll
        for (int i=0;i<10;i++) orow[lane+32*i] = w[lane+32*i]*v[i]*inv;
    }
}

// ---------------- rmsnorm over selected rows -> bf16 h ----------------
__global__ void k_rmsnorm_sel(const float* __restrict__ w) {
    int gw = (blockIdx.x*256 + threadIdx.x) >> 5;
    int lane = threadIdx.x & 31;
    if (gw >= MSEL) return;
    int tok = g_sel[gw];
    __nv_bfloat16* orow = g_h + (size_t)gw*Dv;
    if (tok < 0){
        #pragma unroll
        for (int i=0;i<10;i++) orow[lane+32*i] = __float2bfloat16(0.f);
        return;
    }
    const float* xr = g_x + (size_t)tok*Dv;
    float v[10]; float ss = 0.f;
    #pragma unroll
    for (int i=0;i<10;i++){ v[i] = xr[lane+32*i]; ss = fmaf(v[i],v[i],ss); }
    #pragma unroll
    for (int o=16;o;o>>=1) ss += __shfl_xor_sync(0xffffffffu, ss, o);
    float inv = rsqrtf(ss*(1.f/Dv) + 1e-6f);
    #pragma unroll
    for (int i=0;i<10;i++)
        orow[lane+32*i] = __float2bfloat16(w[lane+32*i]*v[i]*inv);
}

// ---------------- bf16 tensor-core GEMM (128 thr, warp tile 64x64, ldmatrix) ----------------
// ep: 0 = plain fp32 out, 1 = residual add, 2 = MoE scatter add, 4 = QKV+RoPE+Vtr
#define LDH 40
__global__ __launch_bounds__(128) void k_gemm_bf(
    const __nv_bfloat16* __restrict__ A, const __nv_bfloat16* __restrict__ W, void* Cv,
    const float* __restrict__ aux, const float* __restrict__ rowscale,
    const int* __restrict__ sel,
    int M, int N, int K, int ep)
{
    extern __shared__ __nv_bfloat16 smh[];
    const int SA = 128*LDH;
    unsigned base = (unsigned)__cvta_generic_to_shared(smh);
    unsigned Asb[2] = { base, base + (unsigned)SA*2u };
    unsigned Wsb[2] = { base + 2u*SA*2u, base + 3u*SA*2u };

    int tid = threadIdx.x;
    int lane = tid & 31, warp = tid >> 5;
    int wm = warp >> 1, wn = warp & 1;
    int m0 = blockIdx.y*128, n0 = blockIdx.x*128;

    int lrow = tid >> 2;
    int ck  = tid & 3;
    const __nv_bfloat16* Ag = A + (size_t)(m0 + lrow)*K + ck*8;
    int wr0 = n0 + lrow;

    float acc[4][8][4];
    #pragma unroll
    for (int i=0;i<4;i++)
        #pragma unroll
        for (int j=0;j<8;j++)
            #pragma unroll
            for (int c=0;c<4;c++) acc[i][j][c]=0.f;

    int nkb = K >> 5;

    #define LOADTILEB(buf, k0) do {                                               \
        _Pragma("unroll")                                                         \
        for (int i=0;i<4;i++){                                                    \
            int r = lrow + 32*i;                                                  \
            unsigned d = Asb[buf] + (unsigned)((r*LDH + ck*8)*2);                 \
            CPA(d, Ag + (size_t)(32*i)*K + (k0));                                 \
        }                                                                         \
        _Pragma("unroll")                                                         \
        for (int i=0;i<4;i++){                                                    \
            int r = lrow + 32*i;                                                  \
            int wr = wr0 + 32*i;                                                  \
            unsigned sz = (wr < N) ? 16u : 0u;                                    \
            const __nv_bfloat16* src = W + (size_t)(wr < N ? wr : 0)*K + (k0) + ck*8; \
            unsigned d = Wsb[buf] + (unsigned)((r*LDH + ck*8)*2);                 \
            CPAZ(d, src, sz);                                                     \
        }                                                                         \
    } while(0)

    LOADTILEB(0, 0);
    asm volatile("cp.async.commit_group;\n");

    int buf = 0;
    int lr = lane >> 2, lc = lane & 3;
    int arow_l = lane & 15, achk_l = (lane >> 4)*8;
    int brow_l = ((lane >> 4) << 3) + (lane & 7), bchk_l = ((lane >> 3) & 1)*8;
    for (int kb=0; kb<nkb; kb++){
        if (kb+1 < nkb){
            LOADTILEB(buf^1, (kb+1)*32);
            asm volatile("cp.async.commit_group;\n");
            asm volatile("cp.async.wait_group 1;\n");
        } else {
            asm volatile("cp.async.wait_group 0;\n");
        }
        __syncthreads();

        #pragma unroll
        for (int ks=0; ks<2; ks++){
            unsigned a[4][4], b[8][2];
            #pragma unroll
            for (int mf=0; mf<4; mf++){
                unsigned ad = Asb[buf] +
                    (unsigned)(((wm*64 + mf*16 + arow_l)*LDH + ks*16 + achk_l)*2);
                LDSM4(a[mf][0], a[mf][1], a[mf][2], a[mf][3], ad);
            }
            #pragma unroll
            for (int np=0; np<4; np++){
                unsigned bd = Wsb[buf] +
                    (unsigned)(((wn*64 + np*16 + brow_l)*LDH + ks*16 + bchk_l)*2);
                LDSM4(b[2*np][0], b[2*np][1], b[2*np+1][0], b[2*np+1][1], bd);
            }
            #pragma unroll
            for (int mf=0; mf<4; mf++)
                #pragma unroll
                for (int nf=0; nf<8; nf++)
                    MMA_BF16(acc[mf][nf], a[mf][0],a[mf][1],a[mf][2],a[mf][3],
                             b[nf][0], b[nf][1]);
        }
        buf ^= 1;
        __syncthreads();
    }

    if (ep == 4){
        // QKV epilogue: warp tile = one (type, head) 64-dim block.
        int nb = n0 + wn*64;
        if (nb >= N) return;
        int type = nb / 320;            // 0=q 1=k 2=v
        int h = (nb % 320) >> 6;
        #pragma unroll
        for (int mf=0; mf<4; mf++){
            #pragma unroll
            for (int c=0;c<4;c++){
                int m = m0 + wm*64 + mf*16 + lr + ((c>=2)?8:0);
                int s = m & (Sv-1), bb = m >> 11;
                if (type == 2){
                    #pragma unroll
                    for (int nf=0;nf<8;nf++){
                        int d = nf*8 + lc*2 + (c&1);
                        g_v[(((size_t)bb*NHv+h)*HDv + d)*Sv + s] =
                            __float2bfloat16(acc[mf][nf][c]);
                    }
                } else {
                    float* dst = (type==0) ? g_q : g_k;
                    size_t o = (((size_t)bb*NHv+h)*Sv + s)*HDv;
                    #pragma unroll
                    for (int nf=0;nf<4;nf++){
                        int i2 = nf*8 + lc*2 + (c&1);   // d & 31
                        float freq = expf(-(float)(2*i2) * (9.210340371976184f/64.0f));
                        float ang = (float)s * freq;
                        float sn, cs; sincosf(ang, &sn, &cs);
                        float vlo = acc[mf][nf][c], vhi = acc[mf][nf+4][c];
                        dst[o + i2]      = to_tf32(vlo*cs - vhi*sn);
                        dst[o + i2 + 32] = to_tf32(vhi*cs + vlo*sn);
                    }
                }
            }
        }
        return;
    }

    #pragma unroll
    for (int mf=0; mf<4; mf++){
        #pragma unroll
        for (int nf=0; nf<8; nf++){
            int mbase = m0 + wm*64 + mf*16 + lr;
            int nbase = n0 + wn*64 + nf*8 + lc*2;
            #pragma unroll
            for (int c=0;c<4;c++){
                int m = mbase + (c>=2 ? 8 : 0);
                int n = nbase + (c&1);
                if (n < N){
                    float v = acc[mf][nf][c];
                    if (ep==2){
                        int tok = sel[m];
                        if (tok >= 0){
                            size_t o = (size_t)tok*N + n;
                            ((float*)Cv)[o] = aux[o] + rowscale[m]*v;
                        }
                    } else {
                        size_t o = (size_t)m*N + n;
                        if (ep==0) ((float*)Cv)[o] = v;
                        else ((float*)Cv)[o] = aux[o] + v;
                    }
                }
            }
        }
    }
}

// ---------------- fused gate+up+swiglu GEMM (256 thr) ----------------
__global__ __launch_bounds__(256) void k_gemm_gu(
    const __nv_bfloat16* __restrict__ A, const __nv_bfloat16* __restrict__ Wg,
    const __nv_bfloat16* __restrict__ Wu, __nv_bfloat16* __restrict__ C,
    int M, int N, int K)
{
    extern __shared__ __nv_bfloat16 smh[];
    const int SA = 128*LDH;
    unsigned base = (unsigned)__cvta_generic_to_shared(smh);
    unsigned Asb[2] = { base,             base + (unsigned)SA*2u };
    unsigned Gsb[2] = { base + 2u*SA*2u,  base + 3u*SA*2u };
    unsigned Usb[2] = { base + 4u*SA*2u,  base + 5u*SA*2u };

    int tid = threadIdx.x;
    int lane = tid & 31, warp = tid >> 5;
    int wm = warp >> 2, wn2 = warp & 3;
    int m0 = blockIdx.y*128, n0 = blockIdx.x*128;

    int lrow = tid >> 2;
    int ck  = tid & 3;
    const __nv_bfloat16* Ag = A + (size_t)(m0 + lrow)*K + ck*8;
    int wr0 = n0 + lrow;

    float ag[4][4][4], au[4][4][4];
    #pragma unroll
    for (int i=0;i<4;i++)
        #pragma unroll
        for (int j=0;j<4;j++)
            #pragma unroll
            for (int c=0;c<4;c++){ ag[i][j][c]=0.f; au[i][j][c]=0.f; }

    int nkb = K >> 5;

    #define LOADTILEGU(buf, k0) do {                                              \
        _Pragma("unroll")                                                         \
        for (int i=0;i<2;i++){                                                    \
            int r = lrow + 64*i;                                                  \
            unsigned d = Asb[buf] + (unsigned)((r*LDH + ck*8)*2);                 \
            CPA(d, Ag + (size_t)(64*i)*K + (k0));                                 \
        }                                                                         \
        _Pragma("unroll")                                                         \
        for (int i=0;i<2;i++){                                                    \
            int r = lrow + 64*i;                                                  \
            int wr = wr0 + 64*i;                                                  \
            unsigned sz = (wr < N) ? 16u : 0u;                                    \
            size_t so = (size_t)(wr < N ? wr : 0)*K + (k0) + ck*8;                \
            unsigned dg = Gsb[buf] + (unsigned)((r*LDH + ck*8)*2);                 \
            CPAZ(dg, Wg + so, sz);                                                \
            unsigned du = Usb[buf] + (unsigned)((r*LDH + ck*8)*2);                 \
            CPAZ(du, Wu + so, sz);                                                \
        }                                                                         \
    } while(0)

    LOADTILEGU(0, 0);
    asm volatile("cp.async.commit_group;\n");

    int buf = 0;
    int lr = lane >> 2, lc = lane & 3;
    int arow_l = lane & 15, achk_l = (lane >> 4)*8;
    int brow_l = ((lane >> 4) << 3) + (lane & 7), bchk_l = ((lane >> 3) & 1)*8;
    for (int kb=0; kb<nkb; kb++){
        if (kb+1 < nkb){
            LOADTILEGU(buf^1, (kb+1)*32);
            asm volatile("cp.async.commit_group;\n");
            asm volatile("cp.async.wait_group 1;\n");
        } else {
            asm volatile("cp.async.wait_group 0;\n");
        }
        __syncthreads();

        #pragma unroll
        for (int ks=0; ks<2; ks++){
            unsigned a[4][4], bg[4][2], bu[4][2];
            #pragma unroll
            for (int mf=0; mf<4; mf++){
                unsigned ad = Asb[buf] +
                    (unsigned)(((wm*64 + mf*16 + arow_l)*LDH + ks*16 + achk_l)*2);
                LDSM4(a[mf][0], a[mf][1], a[mf][2], a[mf][3], ad);
            }
            #pragma unroll
            for (int np=0; np<2; np++){
                unsigned row = (unsigned)(wn2*32 + np*16 + brow_l);
                unsigned off = (unsigned)((row*LDH + ks*16 + bchk_l)*2);
                LDSM4(bg[2*np][0], bg[2*np][1], bg[2*np+1][0], bg[2*np+1][1], Gsb[buf] + off);
                LDSM4(bu[2*np][0], bu[2*np][1], bu[2*np+1][0], bu[2*np+1][1], Usb[buf] + off);
            }
            #pragma unroll
            for (int mf=0; mf<4; mf++)
                #pragma unroll
                for (int nf=0; nf<4; nf++){
                    MMA_BF16(ag[mf][nf], a[mf][0],a[mf][1],a[mf][2],a[mf][3],
                             bg[nf][0], bg[nf][1]);
                    MMA_BF16(au[mf][nf], a[mf][0],a[mf][1],a[mf][2],a[mf][3],
                             bu[nf][0], bu[nf][1]);
                }
        }
        buf ^= 1;
        __syncthreads();
    }

    #pragma unroll
    for (int mf=0; mf<4; mf++){
        #pragma unroll
        for (int nf=0; nf<4; nf++){
            int mbase = m0 + wm*64 + mf*16 + lr;
            int nbase = n0 + wn2*32 + nf*8 + lc*2;
            #pragma unroll
            for (int c=0;c<4;c++){
                int m = mbase + (c>=2 ? 8 : 0);
                int n = nbase + (c&1);
                if (n < N){
                    float g = ag[mf][nf][c];
                    float u = au[mf][nf][c];
                    C[(size_t)m*N + n] = __float2bfloat16(g * u / (1.f + expf(-g)));
                }
            }
        }
    }
}

// ---------------- flash attention: tf32 QK^T + bf16 PV ----------------
#define APAD 68
#define VPAD 72
__global__ __launch_bounds__(128) void k_attn_tc() {
    extern __shared__ char smraw[];
    float* Qs = (float*)smraw;                            // [64][68] fp32
    float* Ks = Qs + 64*APAD;                             // [64][68] fp32
    __nv_bfloat16* Vt = (__nv_bfloat16*)(Ks + 64*APAD);   // [64][72] bf16 dim-major
    __nv_bfloat16* Ps = Vt + 64*VPAD;                     // [64][72] bf16
    int qt = gridDim.x - 1 - blockIdx.x;   // heavy tiles first
    int h = blockIdx.y, b = blockIdx.z;
    int tid = threadIdx.x, lane = tid & 31, warp = tid >> 5;
    int lr = lane >> 2, lc = lane & 3;
    const size_t headoff = ((size_t)b*NHv + h)*(size_t)Sv*HDv;
    const float* Qg = g_q + headoff + (size_t)qt*64*HDv;
    const float* Kg0 = g_k + headoff;
    const __nv_bfloat16* Vg0 = g_v + headoff;   // [HD][S] bf16

    unsigned psb = (unsigned)__cvta_generic_to_shared(Ps);
    unsigned vtb = (unsigned)__cvta_generic_to_shared(Vt);
    int arow_l = lane & 15, achk_l = (lane >> 4)*8;
    int brow_l = ((lane >> 4) << 3) + (lane & 7), bchk_l = ((lane >> 3) & 1)*8;

    #pragma unroll
    for (int i=0;i<8;i++){
        int idx = (tid + i*128)*4;
        int row = idx >> 6, col = idx & 63;
        *(float4*)(Qs + row*APAD + col) = *(const float4*)(Qg + idx);
    }

    float o[8][4];
    #pragma unroll
    for (int nt=0;nt<8;nt++)
        #pragma unroll
        for (int c=0;c<4;c++) o[nt][c]=0.f;
    float mr0=-1e30f, mr1=-1e30f, ls0=0.f, ls1=0.f;
    int qrow = qt*64 + warp*16 + lr;

    for (int t0=0; t0<=qt; t0++){
        __syncthreads();
        const float* Kg = Kg0 + (size_t)t0*64*HDv;
        #pragma unroll
        for (int i=0;i<8;i++){
            int idx = (tid + i*128)*4;
            int row = idx >> 6, col = idx & 63;
            *(float4*)(Ks + row*APAD + col) = *(const float4*)(Kg + idx);
        }
        #pragma unroll
        for (int i=0;i<4;i++){
            int idx = (tid + i*128)*8;
            int row = idx >> 6, col = idx & 63;
            *(uint4*)(Vt + row*VPAD + col) = *(const uint4*)(Vg0 + (size_t)row*Sv + t0*64 + col);
        }
        __syncthreads();

        // S = Q K^T (tf32)
        float sacc[8][4];
        #pragma unroll
        for (int nt=0;nt<8;nt++)
            #pragma unroll
            for (int c=0;c<4;c++) sacc[nt][c]=0.f;
        #pragma unroll
        for (int ks=0; ks<8; ks++){
            const float* ap = Qs + (warp*16 + lr)*APAD + ks*8 + lc;
            unsigned a0=fbits(ap[0]), a1=fbits(ap[8*APAD]),
                     a2=fbits(ap[4]), a3=fbits(ap[8*APAD+4]);
            #pragma unroll
            for (int nt=0; nt<8; nt++){
                const float* bp = Ks + (nt*8 + lr)*APAD + ks*8 + lc;
                MMA_TF32(sacc[nt], a0,a1,a2,a3, fbits(bp[0]), fbits(bp[4]));
            }
        }

        bool diag = (t0 == qt);
        float mt0=-1e30f, mt1=-1e30f;
        #pragma unroll
        for (int nt=0;nt<8;nt++){
            #pragma unroll
            for (int c=0;c<4;c++){
                float s = sacc[nt][c]*0.125f;
                if (diag){
                    int col = t0*64 + nt*8 + lc*2 + (c&1);
                    int row = qrow + ((c>=2)?8:0);
                    if (col > row) s = -1e30f;
                }
                sacc[nt][c] = s;
                if (c>=2) mt1 = fmaxf(mt1, s); else mt0 = fmaxf(mt0, s);
            }
        }
        mt0 = fmaxf(mt0, __shfl_xor_sync(0xffffffffu, mt0, 1));
        mt0 = fmaxf(mt0, __shfl_xor_sync(0xffffffffu, mt0, 2));
        mt1 = fmaxf(mt1, __shfl_xor_sync(0xffffffffu, mt1, 1));
        mt1 = fmaxf(mt1, __shfl_xor_sync(0xffffffffu, mt1, 2));
        float mn0 = fmaxf(mr0, mt0), mn1 = fmaxf(mr1, mt1);
        float sc0 = __expf(mr0 - mn0), sc1 = __expf(mr1 - mn1);
        ls0 *= sc0; ls1 *= sc1;
        #pragma unroll
        for (int nt=0;nt<8;nt++){
            o[nt][0]*=sc0; o[nt][1]*=sc0; o[nt][2]*=sc1; o[nt][3]*=sc1;
        }
        mr0 = mn0; mr1 = mn1;

        __nv_bfloat16* pr0 = Ps + (warp*16 + lr)*VPAD;
        __nv_bfloat16* pr1 = pr0 + 8*VPAD;
        #pragma unroll
        for (int nt=0;nt<8;nt++){
            int col = nt*8 + lc*2;
            float p0 = __expf(sacc[nt][0] - mn0);
            float p1 = __expf(sacc[nt][1] - mn0);
            float p2 = __expf(sacc[nt][2] - mn1);
            float p3 = __expf(sacc[nt][3] - mn1);
            ls0 += p0 + p1; ls1 += p2 + p3;
            pr0[col]   = __float2bfloat16(p0);
            pr0[col+1] = __float2bfloat16(p1);
            pr1[col]   = __float2bfloat16(p2);
            pr1[col+1] = __float2bfloat16(p3);
        }
        __syncwarp();

        // O += P V   (bf16 m16n8k16, ldmatrix)
        #pragma unroll
        for (int ks=0; ks<4; ks++){
            unsigned a[4];
            unsigned ad = psb + (unsigned)(((warp*16 + arow_l)*VPAD + ks*16 + achk_l)*2);
            LDSM4(a[0], a[1], a[2], a[3], ad);
            unsigned bfr[8][2];
            #pragma unroll
            for (int np=0; np<4; np++){
                unsigned bd = vtb + (unsigned)(((np*16 + brow_l)*VPAD + ks*16 + bchk_l)*2);
                LDSM4(bfr[2*np][0], bfr[2*np][1], bfr[2*np+1][0], bfr[2*np+1][1], bd);
            }
            #pragma unroll
            for (int nt=0; nt<8; nt++)
                MMA_BF16(o[nt], a[0],a[1],a[2],a[3], bfr[nt][0], bfr[nt][1]);
        }
    }

    ls0 += __shfl_xor_sync(0xffffffffu, ls0, 1);
    ls0 += __shfl_xor_sync(0xffffffffu, ls0, 2);
    ls1 += __shfl_xor_sync(0xffffffffu, ls1, 1);
    ls1 += __shfl_xor_sync(0xffffffffu, ls1, 2);
    float inv0 = 1.f/ls0, inv1 = 1.f/ls1;
    int tok0 = b*Sv + qt*64 + warp*16 + lr;
    __nv_bfloat16* out0 = g_att + (size_t)tok0*Dv + h*HDv;
    __nv_bfloat16* out1 = out0 + 8*(size_t)Dv;
    #pragma unroll
    for (int nt=0;nt<8;nt++){
        int col = nt*8 + lc*2;
        out0[col]   = __float2bfloat16(o[nt][0]*inv0);
        out0[col+1] = __float2bfloat16(o[nt][1]*inv0);
        out1[col]   = __float2bfloat16(o[nt][2]*inv1);
        out1[col+1] = __float2bfloat16(o[nt][3]*inv1);
    }
}

// ---------------- router ----------------
__global__ void k_router(const float* __restrict__ rw) {
    int gw = (blockIdx.x*256 + threadIdx.x) >> 5;
    int lane = threadIdx.x & 31;
    if (gw >= TOK) return;
    const float* xr = g_x + (size_t)gw*Dv;
    float s = 0.f;
    #pragma unroll
    for (int i=0;i<10;i++) s = fmaf(xr[lane+32*i], rw[lane+32*i], s);
    #pragma unroll
    for (int o=16;o;o>>=1) s += __shfl_xor_sync(0xffffffffu, s, o);
    if (lane==0) g_probs[gw] = 1.f/(1.f+expf(-s));
}

// ---------------- exact top-k -> compact selection ----------------
__global__ __launch_bounds__(256) void k_topk() {
    __shared__ float p[Sv];
    int b = blockIdx.x, part = blockIdx.y;
    int tid = threadIdx.x;
    for (int i=tid;i<Sv;i+=256) p[i] = g_probs[b*Sv+i];
    __syncthreads();
    int i = part*256 + tid;
    float pi = p[i];
    int cnt = 0;
    #pragma unroll 8
    for (int j=0;j<Sv;j++) {
        float pj = p[j];
        cnt += (pj > pi) || (pj == pi && j < i);
    }
    if (cnt < KSEL){
        g_sel[b*MPAD + cnt] = b*Sv + i;
        g_wselc[b*MPAD + cnt] = pi;
    }
}

// ---------------- driver ----------------
extern "C" void kernel_launch(void* const* d_in, const int* in_sizes, int n_in,
                              void* d_out, int out_size) {
    const int*   ids        = (const int*)d_in[0];
    const int*   iter       = (const int*)d_in[1];
    const float* emb        = (const float*)d_in[2];
    const float* iter_emb   = (const float*)d_in[3];
    const float* attn_norm  = (const float*)d_in[4];
    const float* Wqkv       = (const float*)d_in[5];
    const float* wo         = (const float*)d_in[6];
    const float* router     = (const float*)d_in[7];
    const float* mlp_norm   = (const float*)d_in[8];
    const float* gatew      = (const float*)d_in[9];
    const float* upw        = (const float*)d_in[10];
    const float* downw      = (const float*)d_in[11];
    const float* final_norm = (const float*)d_in[12];
    float* out = (float*)d_out;

    float *xp,*wselp;
    __nv_bfloat16 *hp,*attp,*g2p,*wtp;
    int *selp;
    cudaGetSymbolAddress((void**)&xp,   g_x);
    cudaGetSymbolAddress((void**)&hp,   g_h);
    cudaGetSymbolAddress((void**)&attp, g_att);
    cudaGetSymbolAddress((void**)&g2p,  g_g2);
    cudaGetSymbolAddress((void**)&wselp,g_wselc);
    cudaGetSymbolAddress((void**)&selp, g_sel);
    cudaGetSymbolAddress((void**)&wtp,  g_wt);

    const int SMEMA = 2*64*APAD*4 + 2*64*VPAD*2;   // 53248
    const int SMEMG = 4*128*LDH*2;                 // 40960
    const int SMEMGU = 6*128*LDH*2;                // 61440
    cudaFuncSetAttribute(k_attn_tc, cudaFuncAttributeMaxDynamicSharedMemorySize, SMEMA);
    cudaFuncSetAttribute(k_gemm_bf, cudaFuncAttributeMaxDynamicSharedMemorySize, SMEMG);
    cudaFuncSetAttribute(k_gemm_gu, cudaFuncAttributeMaxDynamicSharedMemorySize, SMEMGU);

    k_cvt<<<(1843200+255)/256,256>>>(Wqkv,  wtp+OFF_QKV,  1843200);
    k_cvt<<<(614400+255)/256, 256>>>(wo,    wtp+OFF_WO,   614400);
    k_cvt<<<(1658880+255)/256,256>>>(gatew, wtp+OFF_GATE, 1658880);
    k_cvt<<<(1658880+255)/256,256>>>(upw,   wtp+OFF_UP,   1658880);
    k_cvt<<<(1658880+255)/256,256>>>(downw, wtp+OFF_DOWN, 1658880);

    k_embed<<<(TOK*Dv+255)/256, 256>>>(ids, iter, emb, iter_emb);
    k_clearpad<<<1, 256>>>();

    dim3 gq((3*Dv+127)/128, TOK/128);
    dim3 g320((Dv+127)/128, TOK/128);
    dim3 gffs((FFv+127)/128, MSEL/128);
    dim3 g320s((Dv+127)/128, MSEL/128);

    for (int l=0;l<NLv;l++) {
        k_rmsnorm<<<TOK/8, 256>>>(xp, attn_norm + (size_t)l*Dv, nullptr, hp);
        k_gemm_bf<<<gq, 128, SMEMG>>>(hp, wtp+OFF_QKV + (size_t)l*960*320, nullptr,
                                      nullptr, nullptr, nullptr, TOK, 3*Dv, Dv, 4);
        k_attn_tc<<<dim3(Sv/64, NHv, Bv), 128, SMEMA>>>();
        k_gemm_bf<<<g320, 128, SMEMG>>>(attp, wtp+OFF_WO + (size_t)l*320*320, xp,
                                        xp, nullptr, nullptr, TOK, Dv, Dv, 1);
        k_router<<<TOK/8, 256>>>(router + (size_t)l*Dv);
        k_topk<<<dim3(Bv, Sv/256), 256>>>();
        k_rmsnorm_sel<<<MSEL/8, 256>>>(mlp_norm + (size_t)l*Dv);
        k_gemm_gu<<<gffs, 256, SMEMGU>>>(hp, wtp+OFF_GATE + (size_t)l*FFv*320,
                                         wtp+OFF_UP + (size_t)l*FFv*320, g2p,
                                         MSEL, FFv, Dv);
        k_gemm_bf<<<g320s, 128, SMEMG>>>(g2p, wtp+OFF_DOWN + (size_t)l*320*FFv, xp,
                                         xp, wselp, selp, MSEL, Dv, FFv, 2);
    }
    k_rmsnorm<<<TOK/8, 256>>>(xp, final_norm, out, nullptr);
}

// round 13
// speedup vs baseline: 1.1278x; 1.1278x over previous
#include <cuda_runtime.h>
#include <cuda_bf16.h>
#include <math.h>

#define Bv 8
#define Sv 2048
#define Dv 320
#define NHv 5
#define HDv 64
#define FFv 864
#define NLv 6
#define NLOOPSv 8
#define TOK (Bv*Sv)
#define KSEL 1638
#define MPAD 1664
#define MSEL (Bv*MPAD)   // 13312

// ---------------- scratch ----------------
__device__ float g_x[TOK*Dv];
__device__ __nv_bfloat16 g_h[TOK*Dv];     // bf16 GEMM A input
__device__ float g_q[Bv*NHv*Sv*HDv];      // tf32 [B][H][S][HD]
__device__ float g_k[Bv*NHv*Sv*HDv];      // tf32 [B][H][S][HD]
__device__ __nv_bfloat16 g_v[Bv*NHv*Sv*HDv]; // bf16 TRANSPOSED [B][H][HD][S]
__device__ __nv_bfloat16 g_att[TOK*Dv];   // bf16 (WO GEMM A)
__device__ float g_probs[TOK];
__device__ int   g_sel[MSEL];
__device__ float g_wselc[MSEL];
__device__ __nv_bfloat16 g_g2[TOK*FFv];   // swiglu act bf16 (down GEMM A)
__device__ float2 g_rope[Sv*32];          // (cos,sin)[s][i2]

#define OFF_QKV  0
#define OFF_WO   1843200
#define OFF_GATE 2457600
#define OFF_UP   4116480
#define OFF_DOWN 5775360
#define TOTW     7434240
__device__ __nv_bfloat16 g_wt[TOTW];

__device__ __forceinline__ float to_tf32(float x){
    unsigned u; asm("cvt.rna.tf32.f32 %0, %1;" : "=r"(u) : "f"(x));
    return __uint_as_float(u);
}
__device__ __forceinline__ unsigned fbits(float x){ return __float_as_uint(x); }

#define MMA_TF32(acc, A0,A1,A2,A3, B0,B1)                                   \
    asm volatile(                                                           \
        "mma.sync.aligned.m16n8k8.row.col.f32.tf32.tf32.f32 "               \
        "{%0,%1,%2,%3},{%4,%5,%6,%7},{%8,%9},{%0,%1,%2,%3};\n"              \
        : "+f"(acc[0]),"+f"(acc[1]),"+f"(acc[2]),"+f"(acc[3])               \
        : "r"(A0),"r"(A1),"r"(A2),"r"(A3),"r"(B0),"r"(B1))

#define MMA_BF16(acc, A0,A1,A2,A3, B0,B1)                                   \
    asm volatile(                                                           \
        "mma.sync.aligned.m16n8k16.row.col.f32.bf16.bf16.f32 "              \
        "{%0,%1,%2,%3},{%4,%5,%6,%7},{%8,%9},{%0,%1,%2,%3};\n"              \
        : "+f"(acc[0]),"+f"(acc[1]),"+f"(acc[2]),"+f"(acc[3])               \
        : "r"(A0),"r"(A1),"r"(A2),"r"(A3),"r"(B0),"r"(B1))

#define LDSM4(r0,r1,r2,r3, addr)                                            \
    asm volatile("ldmatrix.sync.aligned.m8n8.x4.shared.b16 {%0,%1,%2,%3}, [%4];" \
        : "=r"(r0),"=r"(r1),"=r"(r2),"=r"(r3) : "r"(addr))

#define CPA(dst, src) asm volatile("cp.async.cg.shared.global [%0], [%1], 16;\n" :: "r"(dst), "l"(src))
#define CPAZ(dst, src, sz) asm volatile("cp.async.cg.shared.global [%0], [%1], 16, %2;\n" :: "r"(dst), "l"(src), "r"(sz))

// ---------------- conversions / embedding / tables ----------------
__global__ void k_cvt(const float* __restrict__ in, __nv_bfloat16* __restrict__ out, int n){
    int i = blockIdx.x*256 + threadIdx.x;
    if (i < n) out[i] = __float2bfloat16(in[i]);
}

__global__ void k_ropetab(){
    int idx = blockIdx.x*256 + threadIdx.x;
    if (idx >= Sv*32) return;
    int s = idx >> 5, i2 = idx & 31;
    float freq = expf(-(float)(2*i2) * (9.210340371976184f/64.0f));
    float ang = (float)s * freq;
    float sn, cs; sincosf(ang, &sn, &cs);
    g_rope[idx] = make_float2(cs, sn);
}

__global__ void k_embed(const int* __restrict__ ids, const int* __restrict__ iter,
                        const float* __restrict__ emb, const float* __restrict__ iter_emb) {
    int idx = blockIdx.x*256 + threadIdx.x;
    if (idx >= TOK*Dv) return;
    int t = idx / Dv, d = idx - t*Dv;
    float v = emb[(size_t)ids[t]*Dv + d];
    int it = iter[0];
    if (it < NLOOPSv) v += iter_emb[it*Dv + d];
    g_x[idx] = v;
}

__global__ void k_clearpad(){
    int i = threadIdx.x;
    if (i < Bv*(MPAD-KSEL)){
        int b = i/(MPAD-KSEL), j = i%(MPAD-KSEL);
        g_sel[b*MPAD + KSEL + j] = -1;
        g_wselc[b*MPAD + KSEL + j] = 0.f;
    }
}

// ---------------- rmsnorm (dense): writes bf16 (outb) or fp32 (outf) ----------------
__global__ void k_rmsnorm(const float* __restrict__ in, const float* __restrict__ w,
                          float* __restrict__ outf, __nv_bfloat16* __restrict__ outb) {
    int gw = (blockIdx.x*256 + threadIdx.x) >> 5;
    int lane = threadIdx.x & 31;
    if (gw >= TOK) return;
    const float* xr = in + (size_t)gw*Dv;
    float v[10]; float ss = 0.f;
    #pragma unroll
    for (int i=0;i<10;i++){ v[i] = xr[lane+32*i]; ss = fmaf(v[i],v[i],ss); }
    #pragma unroll
    for (int o=16;o;o>>=1) ss += __shfl_xor_sync(0xffffffffu, ss, o);
    float inv = rsqrtf(ss*(1.f/Dv) + 1e-6f);
    if (outb){
        __nv_bfloat16* orow = outb + (size_t)gw*Dv;
        #pragma unroll
        for (int i=0;i<10;i++) orow[lane+32*i] = __float2bfloat16(w[lane+32*i]*v[i]*inv);
    } else {
        float* orow = outf + (size_t)gw*Dv;
        #pragma unroll
        for (int i=0;i<10;i++) orow[lane+32*i] = w[lane+32*i]*v[i]*inv;
    }
}

// ---------------- rmsnorm over selected rows -> bf16 h ----------------
__global__ void k_rmsnorm_sel(const float* __restrict__ w) {
    int gw = (blockIdx.x*256 + threadIdx.x) >> 5;
    int lane = threadIdx.x & 31;
    if (gw >= MSEL) return;
    int tok = g_sel[gw];
    __nv_bfloat16* orow = g_h + (size_t)gw*Dv;
    if (tok < 0){
        #pragma unroll
        for (int i=0;i<10;i++) orow[lane+32*i] = __float2bfloat16(0.f);
        return;
    }
    const float* xr = g_x + (size_t)tok*Dv;
    float v[10]; float ss = 0.f;
    #pragma unroll
    for (int i=0;i<10;i++){ v[i] = xr[lane+32*i]; ss = fmaf(v[i],v[i],ss); }
    #pragma unroll
    for (int o=16;o;o>>=1) ss += __shfl_xor_sync(0xffffffffu, ss, o);
    float inv = rsqrtf(ss*(1.f/Dv) + 1e-6f);
    #pragma unroll
    for (int i=0;i<10;i++)
        orow[lane+32*i] = __float2bfloat16(w[lane+32*i]*v[i]*inv);
}

// ---------------- bf16 tensor-core GEMM (128 thr, warp tile 64x64, ldmatrix) ----------------
// ep: 0 = plain fp32 out, 1 = residual add, 2 = MoE scatter add, 4 = QKV+RoPE+Vtr
#define LDH 40
__global__ __launch_bounds__(128) void k_gemm_bf(
    const __nv_bfloat16* __restrict__ A, const __nv_bfloat16* __restrict__ W, void* Cv,
    const float* __restrict__ aux, const float* __restrict__ rowscale,
    const int* __restrict__ sel,
    int M, int N, int K, int ep)
{
    extern __shared__ __nv_bfloat16 smh[];
    const int SA = 128*LDH;
    unsigned base = (unsigned)__cvta_generic_to_shared(smh);
    unsigned Asb[2] = { base, base + (unsigned)SA*2u };
    unsigned Wsb[2] = { base + 2u*SA*2u, base + 3u*SA*2u };

    int tid = threadIdx.x;
    int lane = tid & 31, warp = tid >> 5;
    int wm = warp >> 1, wn = warp & 1;
    int m0 = blockIdx.y*128, n0 = blockIdx.x*128;

    int lrow = tid >> 2;
    int ck  = tid & 3;
    const __nv_bfloat16* Ag = A + (size_t)(m0 + lrow)*K + ck*8;
    int wr0 = n0 + lrow;

    float acc[4][8][4];
    #pragma unroll
    for (int i=0;i<4;i++)
        #pragma unroll
        for (int j=0;j<8;j++)
            #pragma unroll
            for (int c=0;c<4;c++) acc[i][j][c]=0.f;

    int nkb = K >> 5;

    #define LOADTILEB(buf, k0) do {                                               \
        _Pragma("unroll")                                                         \
        for (int i=0;i<4;i++){                                                    \
            int r = lrow + 32*i;                                                  \
            unsigned d = Asb[buf] + (unsigned)((r*LDH + ck*8)*2);                 \
            CPA(d, Ag + (size_t)(32*i)*K + (k0));                                 \
        }                                                                         \
        _Pragma("unroll")                                                         \
        for (int i=0;i<4;i++){                                                    \
            int r = lrow + 32*i;                                                  \
            int wr = wr0 + 32*i;                                                  \
            unsigned sz = (wr < N) ? 16u : 0u;                                    \
            const __nv_bfloat16* src = W + (size_t)(wr < N ? wr : 0)*K + (k0) + ck*8; \
            unsigned d = Wsb[buf] + (unsigned)((r*LDH + ck*8)*2);                 \
            CPAZ(d, src, sz);                                                     \
        }                                                                         \
    } while(0)

    LOADTILEB(0, 0);
    asm volatile("cp.async.commit_group;\n");

    int buf = 0;
    int lr = lane >> 2, lc = lane & 3;
    int arow_l = lane & 15, achk_l = (lane >> 4)*8;
    int brow_l = ((lane >> 4) << 3) + (lane & 7), bchk_l = ((lane >> 3) & 1)*8;
    for (int kb=0; kb<nkb; kb++){
        if (kb+1 < nkb){
            LOADTILEB(buf^1, (kb+1)*32);
            asm volatile("cp.async.commit_group;\n");
            asm volatile("cp.async.wait_group 1;\n");
        } else {
            asm volatile("cp.async.wait_group 0;\n");
        }
        __syncthreads();

        #pragma unroll
        for (int ks=0; ks<2; ks++){
            unsigned a[4][4], b[8][2];
            #pragma unroll
            for (int mf=0; mf<4; mf++){
                unsigned ad = Asb[buf] +
                    (unsigned)(((wm*64 + mf*16 + arow_l)*LDH + ks*16 + achk_l)*2);
                LDSM4(a[mf][0], a[mf][1], a[mf][2], a[mf][3], ad);
            }
            #pragma unroll
            for (int np=0; np<4; np++){
                unsigned bd = Wsb[buf] +
                    (unsigned)(((wn*64 + np*16 + brow_l)*LDH + ks*16 + bchk_l)*2);
                LDSM4(b[2*np][0], b[2*np][1], b[2*np+1][0], b[2*np+1][1], bd);
            }
            #pragma unroll
            for (int mf=0; mf<4; mf++)
                #pragma unroll
                for (int nf=0; nf<8; nf++)
                    MMA_BF16(acc[mf][nf], a[mf][0],a[mf][1],a[mf][2],a[mf][3],
                             b[nf][0], b[nf][1]);
        }
        buf ^= 1;
        __syncthreads();
    }

    if (ep == 4){
        // QKV epilogue: warp tile = one (type, head) 64-dim block. RoPE via table.
        int nb = n0 + wn*64;
        if (nb >= N) return;
        int type = nb / 320;            // 0=q 1=k 2=v
        int h = (nb % 320) >> 6;
        #pragma unroll
        for (int mf=0; mf<4; mf++){
            #pragma unroll
            for (int c=0;c<4;c++){
                int m = m0 + wm*64 + mf*16 + lr + ((c>=2)?8:0);
                int s = m & (Sv-1), bb = m >> 11;
                if (type == 2){
                    #pragma unroll
                    for (int nf=0;nf<8;nf++){
                        int d = nf*8 + lc*2 + (c&1);
                        g_v[(((size_t)bb*NHv+h)*HDv + d)*Sv + s] =
                            __float2bfloat16(acc[mf][nf][c]);
                    }
                } else {
                    float* dst = (type==0) ? g_q : g_k;
                    size_t o = (((size_t)bb*NHv+h)*Sv + s)*HDv;
                    #pragma unroll
                    for (int nf=0;nf<4;nf++){
                        int i2 = nf*8 + lc*2 + (c&1);   // d & 31
                        float2 rt = g_rope[(s<<5) + i2];
                        float vlo = acc[mf][nf][c], vhi = acc[mf][nf+4][c];
                        dst[o + i2]      = to_tf32(vlo*rt.x - vhi*rt.y);
                        dst[o + i2 + 32] = to_tf32(vhi*rt.x + vlo*rt.y);
                    }
                }
            }
        }
        return;
    }

    #pragma unroll
    for (int mf=0; mf<4; mf++){
        #pragma unroll
        for (int nf=0; nf<8; nf++){
            int mbase = m0 + wm*64 + mf*16 + lr;
            int nbase = n0 + wn*64 + nf*8 + lc*2;
            #pragma unroll
            for (int c=0;c<4;c++){
                int m = mbase + (c>=2 ? 8 : 0);
                int n = nbase + (c&1);
                if (n < N){
                    float v = acc[mf][nf][c];
                    if (ep==2){
                        int tok = sel[m];
                        if (tok >= 0){
                            size_t o = (size_t)tok*N + n;
                            ((float*)Cv)[o] = aux[o] + rowscale[m]*v;
                        }
                    } else {
                        size_t o = (size_t)m*N + n;
                        if (ep==0) ((float*)Cv)[o] = v;
                        else ((float*)Cv)[o] = aux[o] + v;
                    }
                }
            }
        }
    }
}

// ---------------- fused gate+up+swiglu GEMM (256 thr) ----------------
__global__ __launch_bounds__(256) void k_gemm_gu(
    const __nv_bfloat16* __restrict__ A, const __nv_bfloat16* __restrict__ Wg,
    const __nv_bfloat16* __restrict__ Wu, __nv_bfloat16* __restrict__ C,
    int M, int N, int K)
{
    extern __shared__ __nv_bfloat16 smh[];
    const int SA = 128*LDH;
    unsigned base = (unsigned)__cvta_generic_to_shared(smh);
    unsigned Asb[2] = { base,             base + (unsigned)SA*2u };
    unsigned Gsb[2] = { base + 2u*SA*2u,  base + 3u*SA*2u };
    unsigned Usb[2] = { base + 4u*SA*2u,  base + 5u*SA*2u };

    int tid = threadIdx.x;
    int lane = tid & 31, warp = tid >> 5;
    int wm = warp >> 2, wn2 = warp & 3;
    int m0 = blockIdx.y*128, n0 = blockIdx.x*128;

    int lrow = tid >> 2;
    int ck  = tid & 3;
    const __nv_bfloat16* Ag = A + (size_t)(m0 + lrow)*K + ck*8;
    int wr0 = n0 + lrow;

    float ag[4][4][4], au[4][4][4];
    #pragma unroll
    for (int i=0;i<4;i++)
        #pragma unroll
        for (int j=0;j<4;j++)
            #pragma unroll
            for (int c=0;c<4;c++){ ag[i][j][c]=0.f; au[i][j][c]=0.f; }

    int nkb = K >> 5;

    #define LOADTILEGU(buf, k0) do {                                              \
        _Pragma("unroll")                                                         \
        for (int i=0;i<2;i++){                                                    \
            int r = lrow + 64*i;                                                  \
            unsigned d = Asb[buf] + (unsigned)((r*LDH + ck*8)*2);                 \
            CPA(d, Ag + (size_t)(64*i)*K + (k0));                                 \
        }                                                                         \
        _Pragma("unroll")                                                         \
        for (int i=0;i<2;i++){                                                    \
            int r = lrow + 64*i;                                                  \
            int wr = wr0 + 64*i;                                                  \
            unsigned sz = (wr < N) ? 16u : 0u;                                    \
            size_t so = (size_t)(wr < N ? wr : 0)*K + (k0) + ck*8;                \
            unsigned dg = Gsb[buf] + (unsigned)((r*LDH + ck*8)*2);                 \
            CPAZ(dg, Wg + so, sz);                                                \
            unsigned du = Usb[buf] + (unsigned)((r*LDH + ck*8)*2);                 \
            CPAZ(du, Wu + so, sz);                                                \
        }                                                                         \
    } while(0)

    LOADTILEGU(0, 0);
    asm volatile("cp.async.commit_group;\n");

    int buf = 0;
    int lr = lane >> 2, lc = lane & 3;
    int arow_l = lane & 15, achk_l = (lane >> 4)*8;
    int brow_l = ((lane >> 4) << 3) + (lane & 7), bchk_l = ((lane >> 3) & 1)*8;
    for (int kb=0; kb<nkb; kb++){
        if (kb+1 < nkb){
            LOADTILEGU(buf^1, (kb+1)*32);
            asm volatile("cp.async.commit_group;\n");
            asm volatile("cp.async.wait_group 1;\n");
        } else {
            asm volatile("cp.async.wait_group 0;\n");
        }
        __syncthreads();

        #pragma unroll
        for (int ks=0; ks<2; ks++){
            unsigned a[4][4], bg[4][2], bu[4][2];
            #pragma unroll
            for (int mf=0; mf<4; mf++){
                unsigned ad = Asb[buf] +
                    (unsigned)(((wm*64 + mf*16 + arow_l)*LDH + ks*16 + achk_l)*2);
                LDSM4(a[mf][0], a[mf][1], a[mf][2], a[mf][3], ad);
            }
            #pragma unroll
            for (int np=0; np<2; np++){
                unsigned row = (unsigned)(wn2*32 + np*16 + brow_l);
                unsigned off = (unsigned)((row*LDH + ks*16 + bchk_l)*2);
                LDSM4(bg[2*np][0], bg[2*np][1], bg[2*np+1][0], bg[2*np+1][1], Gsb[buf] + off);
                LDSM4(bu[2*np][0], bu[2*np][1], bu[2*np+1][0], bu[2*np+1][1], Usb[buf] + off);
            }
            #pragma unroll
            for (int mf=0; mf<4; mf++)
                #pragma unroll
                for (int nf=0; nf<4; nf++){
                    MMA_BF16(ag[mf][nf], a[mf][0],a[mf][1],a[mf][2],a[mf][3],
                             bg[nf][0], bg[nf][1]);
                    MMA_BF16(au[mf][nf], a[mf][0],a[mf][1],a[mf][2],a[mf][3],
                             bu[nf][0], bu[nf][1]);
                }
        }
        buf ^= 1;
        __syncthreads();
    }

    #pragma unroll
    for (int mf=0; mf<4; mf++){
        #pragma unroll
        for (int nf=0; nf<4; nf++){
            int mbase = m0 + wm*64 + mf*16 + lr;
            int nbase = n0 + wn2*32 + nf*8 + lc*2;
            #pragma unroll
            for (int c=0;c<4;c++){
                int m = mbase + (c>=2 ? 8 : 0);
                int n = nbase + (c&1);
                if (n < N){
                    float g = ag[mf][nf][c];
                    float u = au[mf][nf][c];
                    C[(size_t)m*N + n] = __float2bfloat16(g * u / (1.f + expf(-g)));
                }
            }
        }
    }
}

// ---------------- flash attention: tf32 QK^T + bf16 PV ----------------
#define APAD 68
#define VPAD 72
__global__ __launch_bounds__(128) void k_attn_tc() {
    extern __shared__ char smraw[];
    float* Qs = (float*)smraw;                            // [64][68] fp32
    float* Ks = Qs + 64*APAD;                             // [64][68] fp32
    __nv_bfloat16* Vt = (__nv_bfloat16*)(Ks + 64*APAD);   // [64][72] bf16 dim-major
    __nv_bfloat16* Ps = Vt + 64*VPAD;                     // [64][72] bf16
    int qt = gridDim.x - 1 - blockIdx.x;   // heavy tiles first
    int h = blockIdx.y, b = blockIdx.z;
    int tid = threadIdx.x, lane = tid & 31, warp = tid >> 5;
    int lr = lane >> 2, lc = lane & 3;
    const size_t headoff = ((size_t)b*NHv + h)*(size_t)Sv*HDv;
    const float* Qg = g_q + headoff + (size_t)qt*64*HDv;
    const float* Kg0 = g_k + headoff;
    const __nv_bfloat16* Vg0 = g_v + headoff;   // [HD][S] bf16

    unsigned psb = (unsigned)__cvta_generic_to_shared(Ps);
    unsigned vtb = (unsigned)__cvta_generic_to_shared(Vt);
    int arow_l = lane & 15, achk_l = (lane >> 4)*8;
    int brow_l = ((lane >> 4) << 3) + (lane & 7), bchk_l = ((lane >> 3) & 1)*8;

    #pragma unroll
    for (int i=0;i<8;i++){
        int idx = (tid + i*128)*4;
        int row = idx >> 6, col = idx & 63;
        *(float4*)(Qs + row*APAD + col) = *(const float4*)(Qg + idx);
    }

    float o[8][4];
    #pragma unroll
    for (int nt=0;nt<8;nt++)
        #pragma unroll
        for (int c=0;c<4;c++) o[nt][c]=0.f;
    float mr0=-1e30f, mr1=-1e30f, ls0=0.f, ls1=0.f;
    int qrow = qt*64 + warp*16 + lr;

    for (int t0=0; t0<=qt; t0++){
        __syncthreads();
        const float* Kg = Kg0 + (size_t)t0*64*HDv;
        #pragma unroll
        for (int i=0;i<8;i++){
            int idx = (tid + i*128)*4;
            int row = idx >> 6, col = idx & 63;
            *(float4*)(Ks + row*APAD + col) = *(const float4*)(Kg + idx);
        }
        #pragma unroll
        for (int i=0;i<4;i++){
            int idx = (tid + i*128)*8;
            int row = idx >> 6, col = idx & 63;
            *(uint4*)(Vt + row*VPAD + col) = *(const uint4*)(Vg0 + (size_t)row*Sv + t0*64 + col);
        }
        __syncthreads();

        // S = Q K^T (tf32)
        float sacc[8][4];
        #pragma unroll
        for (int nt=0;nt<8;nt++)
            #pragma unroll
            for (int c=0;c<4;c++) sacc[nt][c]=0.f;
        #pragma unroll
        for (int ks=0; ks<8; ks++){
            const float* ap = Qs + (warp*16 + lr)*APAD + ks*8 + lc;
            unsigned a0=fbits(ap[0]), a1=fbits(ap[8*APAD]),
                     a2=fbits(ap[4]), a3=fbits(ap[8*APAD+4]);
            #pragma unroll
            for (int nt=0; nt<8; nt++){
                const float* bp = Ks + (nt*8 + lr)*APAD + ks*8 + lc;
                MMA_TF32(sacc[nt], a0,a1,a2,a3, fbits(bp[0]), fbits(bp[4]));
            }
        }

        bool diag = (t0 == qt);
        float mt0=-1e30f, mt1=-1e30f;
        #pragma unroll
        for (int nt=0;nt<8;nt++){
            #pragma unroll
            for (int c=0;c<4;c++){
                float s = sacc[nt][c]*0.125f;
                if (diag){
                    int col = t0*64 + nt*8 + lc*2 + (c&1);
                    int row = qrow + ((c>=2)?8:0);
                    if (col > row) s = -1e30f;
                }
                sacc[nt][c] = s;
                if (c>=2) mt1 = fmaxf(mt1, s); else mt0 = fmaxf(mt0, s);
            }
        }
        mt0 = fmaxf(mt0, __shfl_xor_sync(0xffffffffu, mt0, 1));
        mt0 = fmaxf(mt0, __shfl_xor_sync(0xffffffffu, mt0, 2));
        mt1 = fmaxf(mt1, __shfl_xor_sync(0xffffffffu, mt1, 1));
        mt1 = fmaxf(mt1, __shfl_xor_sync(0xffffffffu, mt1, 2));
        float mn0 = fmaxf(mr0, mt0), mn1 = fmaxf(mr1, mt1);
        float sc0 = __expf(mr0 - mn0), sc1 = __expf(mr1 - mn1);
        ls0 *= sc0; ls1 *= sc1;
        #pragma unroll
        for (int nt=0;nt<8;nt++){
            o[nt][0]*=sc0; o[nt][1]*=sc0; o[nt][2]*=sc1; o[nt][3]*=sc1;
        }
        mr0 = mn0; mr1 = mn1;

        __nv_bfloat16* pr0 = Ps + (warp*16 + lr)*VPAD;
        __nv_bfloat16* pr1 = pr0 + 8*VPAD;
        #pragma unroll
        for (int nt=0;nt<8;nt++){
            int col = nt*8 + lc*2;
            float p0 = __expf(sacc[nt][0] - mn0);
            float p1 = __expf(sacc[nt][1] - mn0);
            float p2 = __expf(sacc[nt][2] - mn1);
            float p3 = __expf(sacc[nt][3] - mn1);
            ls0 += p0 + p1; ls1 += p2 + p3;
            pr0[col]   = __float2bfloat16(p0);
            pr0[col+1] = __float2bfloat16(p1);
            pr1[col]   = __float2bfloat16(p2);
            pr1[col+1] = __float2bfloat16(p3);
        }
        __syncwarp();

        // O += P V   (bf16 m16n8k16, ldmatrix)
        #pragma unroll
        for (int ks=0; ks<4; ks++){
            unsigned a[4];
            unsigned ad = psb + (unsigned)(((warp*16 + arow_l)*VPAD + ks*16 + achk_l)*2);
            LDSM4(a[0], a[1], a[2], a[3], ad);
            unsigned bfr[8][2];
            #pragma unroll
            for (int np=0; np<4; np++){
                unsigned bd = vtb + (unsigned)(((np*16 + brow_l)*VPAD + ks*16 + bchk_l)*2);
                LDSM4(bfr[2*np][0], bfr[2*np][1], bfr[2*np+1][0], bfr[2*np+1][1], bd);
            }
            #pragma unroll
            for (int nt=0; nt<8; nt++)
                MMA_BF16(o[nt], a[0],a[1],a[2],a[3], bfr[nt][0], bfr[nt][1]);
        }
    }

    ls0 += __shfl_xor_sync(0xffffffffu, ls0, 1);
    ls0 += __shfl_xor_sync(0xffffffffu, ls0, 2);
    ls1 += __shfl_xor_sync(0xffffffffu, ls1, 1);
    ls1 += __shfl_xor_sync(0xffffffffu, ls1, 2);
    float inv0 = 1.f/ls0, inv1 = 1.f/ls1;
    int tok0 = b*Sv + qt*64 + warp*16 + lr;
    __nv_bfloat16* out0 = g_att + (size_t)tok0*Dv + h*HDv;
    __nv_bfloat16* out1 = out0 + 8*(size_t)Dv;
    #pragma unroll
    for (int nt=0;nt<8;nt++){
        int col = nt*8 + lc*2;
        out0[col]   = __float2bfloat16(o[nt][0]*inv0);
        out0[col+1] = __float2bfloat16(o[nt][1]*inv0);
        out1[col]   = __float2bfloat16(o[nt][2]*inv1);
        out1[col+1] = __float2bfloat16(o[nt][3]*inv1);
    }
}

// ---------------- router ----------------
__global__ void k_router(const float* __restrict__ rw) {
    int gw = (blockIdx.x*256 + threadIdx.x) >> 5;
    int lane = threadIdx.x & 31;
    if (gw >= TOK) return;
    const float* xr = g_x + (size_t)gw*Dv;
    float s = 0.f;
    #pragma unroll
    for (int i=0;i<10;i++) s = fmaf(xr[lane+32*i], rw[lane+32*i], s);
    #pragma unroll
    for (int o=16;o;o>>=1) s += __shfl_xor_sync(0xffffffffu, s, o);
    if (lane==0) g_probs[gw] = 1.f/(1.f+expf(-s));
}

// ---------------- exact top-k -> compact selection ----------------
__global__ __launch_bounds__(256) void k_topk() {
    __shared__ float p[Sv];
    int b = blockIdx.x, part = blockIdx.y;
    int tid = threadIdx.x;
    for (int i=tid;i<Sv;i+=256) p[i] = g_probs[b*Sv+i];
    __syncthreads();
    int i = part*256 + tid;
    float pi = p[i];
    int cnt = 0;
    #pragma unroll 8
    for (int j=0;j<Sv;j++) {
        float pj = p[j];
        cnt += (pj > pi) || (pj == pi && j < i);
    }
    if (cnt < KSEL){
        g_sel[b*MPAD + cnt] = b*Sv + i;
        g_wselc[b*MPAD + cnt] = pi;
    }
}

// ---------------- driver ----------------
extern "C" void kernel_launch(void* const* d_in, const int* in_sizes, int n_in,
                              void* d_out, int out_size) {
    const int*   ids        = (const int*)d_in[0];
    const int*   iter       = (const int*)d_in[1];
    const float* emb        = (const float*)d_in[2];
    const float* iter_emb   = (const float*)d_in[3];
    const float* attn_norm  = (const float*)d_in[4];
    const float* Wqkv       = (const float*)d_in[5];
    const float* wo         = (const float*)d_in[6];
    const float* router     = (const float*)d_in[7];
    const float* mlp_norm   = (const float*)d_in[8];
    const float* gatew      = (const float*)d_in[9];
    const float* upw        = (const float*)d_in[10];
    const float* downw      = (const float*)d_in[11];
    const float* final_norm = (const float*)d_in[12];
    float* out = (float*)d_out;

    float *xp,*wselp;
    __nv_bfloat16 *hp,*attp,*g2p,*wtp;
    int *selp;
    cudaGetSymbolAddress((void**)&xp,   g_x);
    cudaGetSymbolAddress((void**)&hp,   g_h);
    cudaGetSymbolAddress((void**)&attp, g_att);
    cudaGetSymbolAddress((void**)&g2p,  g_g2);
    cudaGetSymbolAddress((void**)&wselp,g_wselc);
    cudaGetSymbolAddress((void**)&selp, g_sel);
    cudaGetSymbolAddress((void**)&wtp,  g_wt);

    const int SMEMA = 2*64*APAD*4 + 2*64*VPAD*2;   // 53248
    const int SMEMG = 4*128*LDH*2;                 // 40960
    const int SMEMGU = 6*128*LDH*2;                // 61440
    cudaFuncSetAttribute(k_attn_tc, cudaFuncAttributeMaxDynamicSharedMemorySize, SMEMA);
    cudaFuncSetAttribute(k_gemm_bf, cudaFuncAttributeMaxDynamicSharedMemorySize, SMEMG);
    cudaFuncSetAttribute(k_gemm_gu, cudaFuncAttributeMaxDynamicSharedMemorySize, SMEMGU);

    k_ropetab<<<(Sv*32+255)/256, 256>>>();
    k_cvt<<<(1843200+255)/256,256>>>(Wqkv,  wtp+OFF_QKV,  1843200);
    k_cvt<<<(614400+255)/256, 256>>>(wo,    wtp+OFF_WO,   614400);
    k_cvt<<<(1658880+255)/256,256>>>(gatew, wtp+OFF_GATE, 1658880);
    k_cvt<<<(1658880+255)/256,256>>>(upw,   wtp+OFF_UP,   1658880);
    k_cvt<<<(1658880+255)/256,256>>>(downw, wtp+OFF_DOWN, 1658880);

    k_embed<<<(TOK*Dv+255)/256, 256>>>(ids, iter, emb, iter_emb);
    k_clearpad<<<1, 256>>>();

    dim3 gq((3*Dv+127)/128, TOK/128);
    dim3 g320((Dv+127)/128, TOK/128);
    dim3 gffs((FFv+127)/128, MSEL/128);
    dim3 g320s((Dv+127)/128, MSEL/128);

    for (int l=0;l<NLv;l++) {
        k_rmsnorm<<<TOK/8, 256>>>(xp, attn_norm + (size_t)l*Dv, nullptr, hp);
        k_gemm_bf<<<gq, 128, SMEMG>>>(hp, wtp+OFF_QKV + (size_t)l*960*320, nullptr,
                                      nullptr, nullptr, nullptr, TOK, 3*Dv, Dv, 4);
        k_attn_tc<<<dim3(Sv/64, NHv, Bv), 128, SMEMA>>>();
        k_gemm_bf<<<g320, 128, SMEMG>>>(attp, wtp+OFF_WO + (size_t)l*320*320, xp,
                                        xp, nullptr, nullptr, TOK, Dv, Dv, 1);
        k_router<<<TOK/8, 256>>>(router + (size_t)l*Dv);
        k_topk<<<dim3(Bv, Sv/256), 256>>>();
        k_rmsnorm_sel<<<MSEL/8, 256>>>(mlp_norm + (size_t)l*Dv);
        k_gemm_gu<<<gffs, 256, SMEMGU>>>(hp, wtp+OFF_GATE + (size_t)l*FFv*320,
                                         wtp+OFF_UP + (size_t)l*FFv*320, g2p,
                                         MSEL, FFv, Dv);
        k_gemm_bf<<<g320s, 128, SMEMG>>>(g2p, wtp+OFF_DOWN + (size_t)l*320*FFv, xp,
                                         xp, wselp, selp, MSEL, Dv, FFv, 2);
    }
    k_rmsnorm<<<TOK/8, 256>>>(xp, final_norm, out, nullptr);
}

// round 14
// speedup vs baseline: 1.1853x; 1.0510x over previous
#include <cuda_runtime.h>
#include <cuda_bf16.h>
#include <math.h>

#define Bv 8
#define Sv 2048
#define Dv 320
#define NHv 5
#define HDv 64
#define FFv 864
#define NLv 6
#define NLOOPSv 8
#define TOK (Bv*Sv)
#define KSEL 1638
#define MPAD 1664
#define MSEL (Bv*MPAD)   // 13312

// ---------------- scratch ----------------
__device__ float g_x[TOK*Dv];
__device__ __nv_bfloat16 g_h[TOK*Dv];
__device__ float g_q[Bv*NHv*Sv*HDv];      // tf32 [B][H][S][HD]
__device__ float g_k[Bv*NHv*Sv*HDv];      // tf32 [B][H][S][HD]
__device__ __nv_bfloat16 g_v[Bv*NHv*Sv*HDv]; // bf16 TRANSPOSED [B][H][HD][S]
__device__ __nv_bfloat16 g_att[TOK*Dv];
__device__ float g_probs[TOK];
__device__ int   g_sel[MSEL];
__device__ float g_wselc[MSEL];
__device__ __nv_bfloat16 g_g2[TOK*FFv];
__device__ float2 g_rope[Sv*32];

#define OFF_QKV  0
#define OFF_WO   1843200
#define OFF_GATE 2457600
#define OFF_UP   4116480
#define OFF_DOWN 5775360
#define TOTW     7434240
__device__ __nv_bfloat16 g_wt[TOTW];

__device__ __forceinline__ float to_tf32(float x){
    unsigned u; asm("cvt.rna.tf32.f32 %0, %1;" : "=r"(u) : "f"(x));
    return __uint_as_float(u);
}
__device__ __forceinline__ unsigned fbits(float x){ return __float_as_uint(x); }
__device__ __forceinline__ unsigned packbf(float lo, float hi){
    __nv_bfloat162 t = __floats2bfloat162_rn(lo, hi);
    return *(unsigned*)&t;
}

#define MMA_TF32(acc, A0,A1,A2,A3, B0,B1)                                   \
    asm volatile(                                                           \
        "mma.sync.aligned.m16n8k8.row.col.f32.tf32.tf32.f32 "               \
        "{%0,%1,%2,%3},{%4,%5,%6,%7},{%8,%9},{%0,%1,%2,%3};\n"              \
        : "+f"(acc[0]),"+f"(acc[1]),"+f"(acc[2]),"+f"(acc[3])               \
        : "r"(A0),"r"(A1),"r"(A2),"r"(A3),"r"(B0),"r"(B1))

#define MMA_BF16(acc, A0,A1,A2,A3, B0,B1)                                   \
    asm volatile(                                                           \
        "mma.sync.aligned.m16n8k16.row.col.f32.bf16.bf16.f32 "              \
        "{%0,%1,%2,%3},{%4,%5,%6,%7},{%8,%9},{%0,%1,%2,%3};\n"              \
        : "+f"(acc[0]),"+f"(acc[1]),"+f"(acc[2]),"+f"(acc[3])               \
        : "r"(A0),"r"(A1),"r"(A2),"r"(A3),"r"(B0),"r"(B1))

#define LDSM4(r0,r1,r2,r3, addr)                                            \
    asm volatile("ldmatrix.sync.aligned.m8n8.x4.shared.b16 {%0,%1,%2,%3}, [%4];" \
        : "=r"(r0),"=r"(r1),"=r"(r2),"=r"(r3) : "r"(addr))

#define CPA(dst, src) asm volatile("cp.async.cg.shared.global [%0], [%1], 16;\n" :: "r"(dst), "l"(src))
#define CPAZ(dst, src, sz) asm volatile("cp.async.cg.shared.global [%0], [%1], 16, %2;\n" :: "r"(dst), "l"(src), "r"(sz))
#define CPCOMMIT() asm volatile("cp.async.commit_group;\n")
#define CPWAIT1() asm volatile("cp.async.wait_group 1;\n")

// ---------------- conversions / embedding / tables ----------------
__global__ void k_cvt(const float* __restrict__ in, __nv_bfloat16* __restrict__ out, int n){
    int i = blockIdx.x*256 + threadIdx.x;
    if (i < n) out[i] = __float2bfloat16(in[i]);
}

__global__ void k_ropetab(){
    int idx = blockIdx.x*256 + threadIdx.x;
    if (idx >= Sv*32) return;
    int s = idx >> 5, i2 = idx & 31;
    float freq = expf(-(float)(2*i2) * (9.210340371976184f/64.0f));
    float ang = (float)s * freq;
    float sn, cs; sincosf(ang, &sn, &cs);
    g_rope[idx] = make_float2(cs, sn);
}

__global__ void k_embed(const int* __restrict__ ids, const int* __restrict__ iter,
                        const float* __restrict__ emb, const float* __restrict__ iter_emb) {
    int idx = blockIdx.x*256 + threadIdx.x;
    if (idx >= TOK*Dv) return;
    int t = idx / Dv, d = idx - t*Dv;
    float v = emb[(size_t)ids[t]*Dv + d];
    int it = iter[0];
    if (it < NLOOPSv) v += iter_emb[it*Dv + d];
    g_x[idx] = v;
}

__global__ void k_clearpad(){
    int i = threadIdx.x;
    if (i < Bv*(MPAD-KSEL)){
        int b = i/(MPAD-KSEL), j = i%(MPAD-KSEL);
        g_sel[b*MPAD + KSEL + j] = -1;
        g_wselc[b*MPAD + KSEL + j] = 0.f;
    }
}

// ---------------- rmsnorm (dense) ----------------
__global__ void k_rmsnorm(const float* __restrict__ in, const float* __restrict__ w,
                          float* __restrict__ outf, __nv_bfloat16* __restrict__ outb) {
    int gw = (blockIdx.x*256 + threadIdx.x) >> 5;
    int lane = threadIdx.x & 31;
    if (gw >= TOK) return;
    const float* xr = in + (size_t)gw*Dv;
    float v[10]; float ss = 0.f;
    #pragma unroll
    for (int i=0;i<10;i++){ v[i] = xr[lane+32*i]; ss = fmaf(v[i],v[i],ss); }
    #pragma unroll
    for (int o=16;o;o>>=1) ss += __shfl_xor_sync(0xffffffffu, ss, o);
    float inv = rsqrtf(ss*(1.f/Dv) + 1e-6f);
    if (outb){
        __nv_bfloat16* orow = outb + (size_t)gw*Dv;
        #pragma unroll
        for (int i=0;i<10;i++) orow[lane+32*i] = __float2bfloat16(w[lane+32*i]*v[i]*inv);
    } else {
        float* orow = outf + (size_t)gw*Dv;
        #pragma unroll
        for (int i=0;i<10;i++) orow[lane+32*i] = w[lane+32*i]*v[i]*inv;
    }
}

// ---------------- rmsnorm over selected rows -> bf16 h ----------------
__global__ void k_rmsnorm_sel(const float* __restrict__ w) {
    int gw = (blockIdx.x*256 + threadIdx.x) >> 5;
    int lane = threadIdx.x & 31;
    if (gw >= MSEL) return;
    int tok = g_sel[gw];
    __nv_bfloat16* orow = g_h + (size_t)gw*Dv;
    if (tok < 0){
        #pragma unroll
        for (int i=0;i<10;i++) orow[lane+32*i] = __float2bfloat16(0.f);
        return;
    }
    const float* xr = g_x + (size_t)tok*Dv;
    float v[10]; float ss = 0.f;
    #pragma unroll
    for (int i=0;i<10;i++){ v[i] = xr[lane+32*i]; ss = fmaf(v[i],v[i],ss); }
    #pragma unroll
    for (int o=16;o;o>>=1) ss += __shfl_xor_sync(0xffffffffu, ss, o);
    float inv = rsqrtf(ss*(1.f/Dv) + 1e-6f);
    #pragma unroll
    for (int i=0;i<10;i++)
        orow[lane+32*i] = __float2bfloat16(w[lane+32*i]*v[i]*inv);
}

// ---------------- bf16 GEMM (128 thr, warp 64x64, ldmatrix, 3-stage cp.async) ----------------
// ep: 0 plain, 1 residual add, 2 MoE scatter add, 4 QKV+RoPE+Vtr
#define LDH 40
__global__ __launch_bounds__(128) void k_gemm_bf(
    const __nv_bfloat16* __restrict__ A, const __nv_bfloat16* __restrict__ W, void* Cv,
    const float* __restrict__ aux, const float* __restrict__ rowscale,
    const int* __restrict__ sel,
    int M, int N, int K, int ep)
{
    extern __shared__ __nv_bfloat16 smh[];
    const int SA = 128*LDH;
    unsigned base = (unsigned)__cvta_generic_to_shared(smh);
    unsigned Asb[3] = { base, base + (unsigned)(2*SA)*2u, base + (unsigned)(4*SA)*2u };
    unsigned Wsb[3] = { base + (unsigned)SA*2u, base + (unsigned)(3*SA)*2u, base + (unsigned)(5*SA)*2u };

    int tid = threadIdx.x;
    int lane = tid & 31, warp = tid >> 5;
    int wm = warp >> 1, wn = warp & 1;
    int m0 = blockIdx.y*128, n0 = blockIdx.x*128;

    int lrow = tid >> 2;
    int ck  = tid & 3;
    const __nv_bfloat16* Ag = A + (size_t)(m0 + lrow)*K + ck*8;
    int wr0 = n0 + lrow;

    float acc[4][8][4];
    #pragma unroll
    for (int i=0;i<4;i++)
        #pragma unroll
        for (int j=0;j<8;j++)
            #pragma unroll
            for (int c=0;c<4;c++) acc[i][j][c]=0.f;

    int nkb = K >> 5;

    #define LOADTILEB(st, k0) do {                                                \
        _Pragma("unroll")                                                         \
        for (int i=0;i<4;i++){                                                    \
            int r = lrow + 32*i;                                                  \
            unsigned d = Asb[st] + (unsigned)((r*LDH + ck*8)*2);                  \
            CPA(d, Ag + (size_t)(32*i)*K + (k0));                                 \
        }                                                                         \
        _Pragma("unroll")                                                         \
        for (int i=0;i<4;i++){                                                    \
            int r = lrow + 32*i;                                                  \
            int wr = wr0 + 32*i;                                                  \
            unsigned sz = (wr < N) ? 16u : 0u;                                    \
            const __nv_bfloat16* src = W + (size_t)(wr < N ? wr : 0)*K + (k0) + ck*8; \
            unsigned d = Wsb[st] + (unsigned)((r*LDH + ck*8)*2);                  \
            CPAZ(d, src, sz);                                                     \
        }                                                                         \
    } while(0)

    LOADTILEB(0, 0);
    CPCOMMIT();
    if (nkb > 1) LOADTILEB(1, 32);
    CPCOMMIT();

    int lr = lane >> 2, lc = lane & 3;
    int arow_l = lane & 15, achk_l = (lane >> 4)*8;
    int brow_l = ((lane >> 4) << 3) + (lane & 7), bchk_l = ((lane >> 3) & 1)*8;
    int st = 0;
    for (int kb=0; kb<nkb; kb++){
        CPWAIT1();
        __syncthreads();
        if (kb+2 < nkb){
            int st2 = (st+2 >= 3) ? st-1 : st+2;
            LOADTILEB(st2, (kb+2)*32);
        }
        CPCOMMIT();

        #pragma unroll
        for (int ks=0; ks<2; ks++){
            unsigned a[4][4], b[8][2];
            #pragma unroll
            for (int mf=0; mf<4; mf++){
                unsigned ad = Asb[st] +
                    (unsigned)(((wm*64 + mf*16 + arow_l)*LDH + ks*16 + achk_l)*2);
                LDSM4(a[mf][0], a[mf][1], a[mf][2], a[mf][3], ad);
            }
            #pragma unroll
            for (int np=0; np<4; np++){
                unsigned bd = Wsb[st] +
                    (unsigned)(((wn*64 + np*16 + brow_l)*LDH + ks*16 + bchk_l)*2);
                LDSM4(b[2*np][0], b[2*np][1], b[2*np+1][0], b[2*np+1][1], bd);
            }
            #pragma unroll
            for (int mf=0; mf<4; mf++)
                #pragma unroll
                for (int nf=0; nf<8; nf++)
                    MMA_BF16(acc[mf][nf], a[mf][0],a[mf][1],a[mf][2],a[mf][3],
                             b[nf][0], b[nf][1]);
        }
        st = (st+1 >= 3) ? 0 : st+1;
    }

    if (ep == 4){
        int nb = n0 + wn*64;
        if (nb >= N) return;
        int type = nb / 320;
        int h = (nb % 320) >> 6;
        #pragma unroll
        for (int mf=0; mf<4; mf++){
            #pragma unroll
            for (int c=0;c<4;c++){
                int m = m0 + wm*64 + mf*16 + lr + ((c>=2)?8:0);
                int s = m & (Sv-1), bb = m >> 11;
                if (type == 2){
                    #pragma unroll
                    for (int nf=0;nf<8;nf++){
                        int d = nf*8 + lc*2 + (c&1);
                        g_v[(((size_t)bb*NHv+h)*HDv + d)*Sv + s] =
                            __float2bfloat16(acc[mf][nf][c]);
                    }
                } else {
                    float* dst = (type==0) ? g_q : g_k;
                    size_t o = (((size_t)bb*NHv+h)*Sv + s)*HDv;
                    #pragma unroll
                    for (int nf=0;nf<4;nf++){
                        int i2 = nf*8 + lc*2 + (c&1);
                        float2 rt = g_rope[(s<<5) + i2];
                        float vlo = acc[mf][nf][c], vhi = acc[mf][nf+4][c];
                        dst[o + i2]      = to_tf32(vlo*rt.x - vhi*rt.y);
                        dst[o + i2 + 32] = to_tf32(vhi*rt.x + vlo*rt.y);
                    }
                }
            }
        }
        return;
    }

    #pragma unroll
    for (int mf=0; mf<4; mf++){
        #pragma unroll
        for (int nf=0; nf<8; nf++){
            int mbase = m0 + wm*64 + mf*16 + lr;
            int nbase = n0 + wn*64 + nf*8 + lc*2;
            #pragma unroll
            for (int c=0;c<4;c++){
                int m = mbase + (c>=2 ? 8 : 0);
                int n = nbase + (c&1);
                if (n < N){
                    float v = acc[mf][nf][c];
                    if (ep==2){
                        int tok = sel[m];
                        if (tok >= 0){
                            size_t o = (size_t)tok*N + n;
                            ((float*)Cv)[o] = aux[o] + rowscale[m]*v;
                        }
                    } else {
                        size_t o = (size_t)m*N + n;
                        if (ep==0) ((float*)Cv)[o] = v;
                        else ((float*)Cv)[o] = aux[o] + v;
                    }
                }
            }
        }
    }
}

// ---------------- fused gate+up+swiglu GEMM (256 thr, 3-stage) ----------------
__global__ __launch_bounds__(256) void k_gemm_gu(
    const __nv_bfloat16* __restrict__ A, const __nv_bfloat16* __restrict__ Wg,
    const __nv_bfloat16* __restrict__ Wu, __nv_bfloat16* __restrict__ C,
    int M, int N, int K)
{
    extern __shared__ __nv_bfloat16 smh[];
    const int SA = 128*LDH;
    unsigned base = (unsigned)__cvta_generic_to_shared(smh);
    unsigned Asb[3] = { base,                      base + (unsigned)(3*SA)*2u, base + (unsigned)(6*SA)*2u };
    unsigned Gsb[3] = { base + (unsigned)SA*2u,    base + (unsigned)(4*SA)*2u, base + (unsigned)(7*SA)*2u };
    unsigned Usb[3] = { base + (unsigned)(2*SA)*2u,base + (unsigned)(5*SA)*2u, base + (unsigned)(8*SA)*2u };

    int tid = threadIdx.x;
    int lane = tid & 31, warp = tid >> 5;
    int wm = warp >> 2, wn2 = warp & 3;
    int m0 = blockIdx.y*128, n0 = blockIdx.x*128;

    int lrow = tid >> 2;
    int ck  = tid & 3;
    const __nv_bfloat16* Ag = A + (size_t)(m0 + lrow)*K + ck*8;
    int wr0 = n0 + lrow;

    float ag[4][4][4], au[4][4][4];
    #pragma unroll
    for (int i=0;i<4;i++)
        #pragma unroll
        for (int j=0;j<4;j++)
            #pragma unroll
            for (int c=0;c<4;c++){ ag[i][j][c]=0.f; au[i][j][c]=0.f; }

    int nkb = K >> 5;

    #define LOADTILEGU(st, k0) do {                                               \
        _Pragma("unroll")                                                         \
        for (int i=0;i<2;i++){                                                    \
            int r = lrow + 64*i;                                                  \
            unsigned d = Asb[st] + (unsigned)((r*LDH + ck*8)*2);                  \
            CPA(d, Ag + (size_t)(64*i)*K + (k0));                                 \
        }                                                                         \
        _Pragma("unroll")                                                         \
        for (int i=0;i<2;i++){                                                    \
            int r = lrow + 64*i;                                                  \
            int wr = wr0 + 64*i;                                                  \
            unsigned sz = (wr < N) ? 16u : 0u;                                    \
            size_t so = (size_t)(wr < N ? wr : 0)*K + (k0) + ck*8;                \
            unsigned dg = Gsb[st] + (unsigned)((r*LDH + ck*8)*2);                  \
            CPAZ(dg, Wg + so, sz);                                                \
            unsigned du = Usb[st] + (unsigned)((r*LDH + ck*8)*2);                  \
            CPAZ(du, Wu + so, sz);                                                \
        }                                                                         \
    } while(0)

    LOADTILEGU(0, 0);
    CPCOMMIT();
    if (nkb > 1) LOADTILEGU(1, 32);
    CPCOMMIT();

    int lr = lane >> 2, lc = lane & 3;
    int arow_l = lane & 15, achk_l = (lane >> 4)*8;
    int brow_l = ((lane >> 4) << 3) + (lane & 7), bchk_l = ((lane >> 3) & 1)*8;
    int st = 0;
    for (int kb=0; kb<nkb; kb++){
        CPWAIT1();
        __syncthreads();
        if (kb+2 < nkb){
            int st2 = (st+2 >= 3) ? st-1 : st+2;
            LOADTILEGU(st2, (kb+2)*32);
        }
        CPCOMMIT();

        #pragma unroll
        for (int ks=0; ks<2; ks++){
            unsigned a[4][4], bg[4][2], bu[4][2];
            #pragma unroll
            for (int mf=0; mf<4; mf++){
                unsigned ad = Asb[st] +
                    (unsigned)(((wm*64 + mf*16 + arow_l)*LDH + ks*16 + achk_l)*2);
                LDSM4(a[mf][0], a[mf][1], a[mf][2], a[mf][3], ad);
            }
            #pragma unroll
            for (int np=0; np<2; np++){
                unsigned row = (unsigned)(wn2*32 + np*16 + brow_l);
                unsigned off = (unsigned)((row*LDH + ks*16 + bchk_l)*2);
                LDSM4(bg[2*np][0], bg[2*np][1], bg[2*np+1][0], bg[2*np+1][1], Gsb[st] + off);
                LDSM4(bu[2*np][0], bu[2*np][1], bu[2*np+1][0], bu[2*np+1][1], Usb[st] + off);
            }
            #pragma unroll
            for (int mf=0; mf<4; mf++)
                #pragma unroll
                for (int nf=0; nf<4; nf++){
                    MMA_BF16(ag[mf][nf], a[mf][0],a[mf][1],a[mf][2],a[mf][3],
                             bg[nf][0], bg[nf][1]);
                    MMA_BF16(au[mf][nf], a[mf][0],a[mf][1],a[mf][2],a[mf][3],
                             bu[nf][0], bu[nf][1]);
                }
        }
        st = (st+1 >= 3) ? 0 : st+1;
    }

    #pragma unroll
    for (int mf=0; mf<4; mf++){
        #pragma unroll
        for (int nf=0; nf<4; nf++){
            int mbase = m0 + wm*64 + mf*16 + lr;
            int nbase = n0 + wn2*32 + nf*8 + lc*2;
            #pragma unroll
            for (int c=0;c<4;c++){
                int m = mbase + (c>=2 ? 8 : 0);
                int n = nbase + (c&1);
                if (n < N){
                    float g = ag[mf][nf][c];
                    float u = au[mf][nf][c];
                    C[(size_t)m*N + n] = __float2bfloat16(g * u / (1.f + expf(-g)));
                }
            }
        }
    }
}

// ---------------- flash attention: tf32 QK^T + bf16 PV (P in registers) ----------------
#define APAD 68
#define VPAD 72
__global__ __launch_bounds__(128) void k_attn_tc() {
    extern __shared__ char smraw[];
    float* Qs = (float*)smraw;                            // [64][68] fp32
    float* Ks = Qs + 64*APAD;                             // [64][68] fp32
    __nv_bfloat16* Vt = (__nv_bfloat16*)(Ks + 64*APAD);   // [64][72] bf16 dim-major
    int qt = gridDim.x - 1 - blockIdx.x;   // heavy tiles first
    int h = blockIdx.y, b = blockIdx.z;
    int tid = threadIdx.x, lane = tid & 31, warp = tid >> 5;
    int lr = lane >> 2, lc = lane & 3;
    const size_t headoff = ((size_t)b*NHv + h)*(size_t)Sv*HDv;
    const float* Qg = g_q + headoff + (size_t)qt*64*HDv;
    const float* Kg0 = g_k + headoff;
    const __nv_bfloat16* Vg0 = g_v + headoff;   // [HD][S] bf16

    unsigned vtb = (unsigned)__cvta_generic_to_shared(Vt);
    int brow_l = ((lane >> 4) << 3) + (lane & 7), bchk_l = ((lane >> 3) & 1)*8;

    #pragma unroll
    for (int i=0;i<8;i++){
        int idx = (tid + i*128)*4;
        int row = idx >> 6, col = idx & 63;
        *(float4*)(Qs + row*APAD + col) = *(const float4*)(Qg + idx);
    }

    float o[8][4];
    #pragma unroll
    for (int nt=0;nt<8;nt++)
        #pragma unroll
        for (int c=0;c<4;c++) o[nt][c]=0.f;
    float mr0=-1e30f, mr1=-1e30f, ls0=0.f, ls1=0.f;
    int qrow = qt*64 + warp*16 + lr;

    for (int t0=0; t0<=qt; t0++){
        __syncthreads();
        const float* Kg = Kg0 + (size_t)t0*64*HDv;
        #pragma unroll
        for (int i=0;i<8;i++){
            int idx = (tid + i*128)*4;
            int row = idx >> 6, col = idx & 63;
            *(float4*)(Ks + row*APAD + col) = *(const float4*)(Kg + idx);
        }
        #pragma unroll
        for (int i=0;i<4;i++){
            int idx = (tid + i*128)*8;
            int row = idx >> 6, col = idx & 63;
            *(uint4*)(Vt + row*VPAD + col) = *(const uint4*)(Vg0 + (size_t)row*Sv + t0*64 + col);
        }
        __syncthreads();

        // S = Q K^T (tf32)
        float sacc[8][4];
        #pragma unroll
        for (int nt=0;nt<8;nt++)
            #pragma unroll
            for (int c=0;c<4;c++) sacc[nt][c]=0.f;
        #pragma unroll
        for (int ks=0; ks<8; ks++){
            const float* ap = Qs + (warp*16 + lr)*APAD + ks*8 + lc;
            unsigned a0=fbits(ap[0]), a1=fbits(ap[8*APAD]),
                     a2=fbits(ap[4]), a3=fbits(ap[8*APAD+4]);
            #pragma unroll
            for (int nt=0; nt<8; nt++){
                const float* bp = Ks + (nt*8 + lr)*APAD + ks*8 + lc;
                MMA_TF32(sacc[nt], a0,a1,a2,a3, fbits(bp[0]), fbits(bp[4]));
            }
        }

        bool diag = (t0 == qt);
        float mt0=-1e30f, mt1=-1e30f;
        #pragma unroll
        for (int nt=0;nt<8;nt++){
            #pragma unroll
            for (int c=0;c<4;c++){
                float s = sacc[nt][c]*0.125f;
                if (diag){
                    int col = t0*64 + nt*8 + lc*2 + (c&1);
                    int row = qrow + ((c>=2)?8:0);
                    if (col > row) s = -1e30f;
                }
                sacc[nt][c] = s;
                if (c>=2) mt1 = fmaxf(mt1, s); else mt0 = fmaxf(mt0, s);
            }
        }
        mt0 = fmaxf(mt0, __shfl_xor_sync(0xffffffffu, mt0, 1));
        mt0 = fmaxf(mt0, __shfl_xor_sync(0xffffffffu, mt0, 2));
        mt1 = fmaxf(mt1, __shfl_xor_sync(0xffffffffu, mt1, 1));
        mt1 = fmaxf(mt1, __shfl_xor_sync(0xffffffffu, mt1, 2));
        float mn0 = fmaxf(mr0, mt0), mn1 = fmaxf(mr1, mt1);
        float sc0 = __expf(mr0 - mn0), sc1 = __expf(mr1 - mn1);
        ls0 *= sc0; ls1 *= sc1;
        #pragma unroll
        for (int nt=0;nt<8;nt++){
            o[nt][0]*=sc0; o[nt][1]*=sc0; o[nt][2]*=sc1; o[nt][3]*=sc1;
        }
        mr0 = mn0; mr1 = mn1;

        // exp -> P kept in registers (sacc)
        #pragma unroll
        for (int nt=0;nt<8;nt++){
            float p0 = __expf(sacc[nt][0] - mn0);
            float p1 = __expf(sacc[nt][1] - mn0);
            float p2 = __expf(sacc[nt][2] - mn1);
            float p3 = __expf(sacc[nt][3] - mn1);
            ls0 += p0 + p1; ls1 += p2 + p3;
            sacc[nt][0]=p0; sacc[nt][1]=p1; sacc[nt][2]=p2; sacc[nt][3]=p3;
        }

        // O += P V   (bf16 m16n8k16; A-fragments packed from registers)
        #pragma unroll
        for (int ks=0; ks<4; ks++){
            unsigned a0 = packbf(sacc[2*ks][0],   sacc[2*ks][1]);
            unsigned a1 = packbf(sacc[2*ks][2],   sacc[2*ks][3]);
            unsigned a2 = packbf(sacc[2*ks+1][0], sacc[2*ks+1][1]);
            unsigned a3 = packbf(sacc[2*ks+1][2], sacc[2*ks+1][3]);
            unsigned bfr[8][2];
            #pragma unroll
            for (int np=0; np<4; np++){
                unsigned bd = vtb + (unsigned)(((np*16 + brow_l)*VPAD + ks*16 + bchk_l)*2);
                LDSM4(bfr[2*np][0], bfr[2*np][1], bfr[2*np+1][0], bfr[2*np+1][1], bd);
            }
            #pragma unroll
            for (int nt=0; nt<8; nt++)
                MMA_BF16(o[nt], a0,a1,a2,a3, bfr[nt][0], bfr[nt][1]);
        }
    }

    ls0 += __shfl_xor_sync(0xffffffffu, ls0, 1);
    ls0 += __shfl_xor_sync(0xffffffffu, ls0, 2);
    ls1 += __shfl_xor_sync(0xffffffffu, ls1, 1);
    ls1 += __shfl_xor_sync(0xffffffffu, ls1, 2);
    float inv0 = 1.f/ls0, inv1 = 1.f/ls1;
    int tok0 = b*Sv + qt*64 + warp*16 + lr;
    __nv_bfloat16* out0 = g_att + (size_t)tok0*Dv + h*HDv;
    __nv_bfloat16* out1 = out0 + 8*(size_t)Dv;
    #pragma unroll
    for (int nt=0;nt<8;nt++){
        int col = nt*8 + lc*2;
        out0[col]   = __float2bfloat16(o[nt][0]*inv0);
        out0[col+1] = __float2bfloat16(o[nt][1]*inv0);
        out1[col]   = __float2bfloat16(o[nt][2]*inv1);
        out1[col+1] = __float2bfloat16(o[nt][3]*inv1);
    }
}

// ---------------- router ----------------
__global__ void k_router(const float* __restrict__ rw) {
    int gw = (blockIdx.x*256 + threadIdx.x) >> 5;
    int lane = threadIdx.x & 31;
    if (gw >= TOK) return;
    const float* xr = g_x + (size_t)gw*Dv;
    float s = 0.f;
    #pragma unroll
    for (int i=0;i<10;i++) s = fmaf(xr[lane+32*i], rw[lane+32*i], s);
    #pragma unroll
    for (int o=16;o;o>>=1) s += __shfl_xor_sync(0xffffffffu, s, o);
    if (lane==0) g_probs[gw] = 1.f/(1.f+expf(-s));
}

// ---------------- exact top-k -> compact selection ----------------
__global__ __launch_bounds__(256) void k_topk() {
    __shared__ float p[Sv];
    int b = blockIdx.x, part = blockIdx.y;
    int tid = threadIdx.x;
    for (int i=tid;i<Sv;i+=256) p[i] = g_probs[b*Sv+i];
    __syncthreads();
    int i = part*256 + tid;
    float pi = p[i];
    int cnt = 0;
    #pragma unroll 8
    for (int j=0;j<Sv;j++) {
        float pj = p[j];
        cnt += (pj > pi) || (pj == pi && j < i);
    }
    if (cnt < KSEL){
        g_sel[b*MPAD + cnt] = b*Sv + i;
        g_wselc[b*MPAD + cnt] = pi;
    }
}

// ---------------- driver ----------------
extern "C" void kernel_launch(void* const* d_in, const int* in_sizes, int n_in,
                              void* d_out, int out_size) {
    const int*   ids        = (const int*)d_in[0];
    const int*   iter       = (const int*)d_in[1];
    const float* emb        = (const float*)d_in[2];
    const float* iter_emb   = (const float*)d_in[3];
    const float* attn_norm  = (const float*)d_in[4];
    const float* Wqkv       = (const float*)d_in[5];
    const float* wo         = (const float*)d_in[6];
    const float* router     = (const float*)d_in[7];
    const float* mlp_norm   = (const float*)d_in[8];
    const float* gatew      = (const float*)d_in[9];
    const float* upw        = (const float*)d_in[10];
    const float* downw      = (const float*)d_in[11];
    const float* final_norm = (const float*)d_in[12];
    float* out = (float*)d_out;

    float *xp,*wselp;
    __nv_bfloat16 *hp,*attp,*g2p,*wtp;
    int *selp;
    cudaGetSymbolAddress((void**)&xp,   g_x);
    cudaGetSymbolAddress((void**)&hp,   g_h);
    cudaGetSymbolAddress((void**)&attp, g_att);
    cudaGetSymbolAddress((void**)&g2p,  g_g2);
    cudaGetSymbolAddress((void**)&wselp,g_wselc);
    cudaGetSymbolAddress((void**)&selp, g_sel);
    cudaGetSymbolAddress((void**)&wtp,  g_wt);

    const int SMEMA = 2*64*APAD*4 + 64*VPAD*2;     // 44032
    const int SMEMG = 6*128*LDH*2;                 // 61440
    const int SMEMGU = 9*128*LDH*2;                // 92160
    cudaFuncSetAttribute(k_attn_tc, cudaFuncAttributeMaxDynamicSharedMemorySize, SMEMA);
    cudaFuncSetAttribute(k_gemm_bf, cudaFuncAttributeMaxDynamicSharedMemorySize, SMEMG);
    cudaFuncSetAttribute(k_gemm_gu, cudaFuncAttributeMaxDynamicSharedMemorySize, SMEMGU);

    k_ropetab<<<(Sv*32+255)/256, 256>>>();
    k_cvt<<<(1843200+255)/256,256>>>(Wqkv,  wtp+OFF_QKV,  1843200);
    k_cvt<<<(614400+255)/256, 256>>>(wo,    wtp+OFF_WO,   614400);
    k_cvt<<<(1658880+255)/256,256>>>(gatew, wtp+OFF_GATE, 1658880);
    k_cvt<<<(1658880+255)/256,256>>>(upw,   wtp+OFF_UP,   1658880);
    k_cvt<<<(1658880+255)/256,256>>>(downw, wtp+OFF_DOWN, 1658880);

    k_embed<<<(TOK*Dv+255)/256, 256>>>(ids, iter, emb, iter_emb);
    k_clearpad<<<1, 256>>>();

    dim3 gq((3*Dv+127)/128, TOK/128);
    dim3 g320((Dv+127)/128, TOK/128);
    dim3 gffs((FFv+127)/128, MSEL/128);
    dim3 g320s((Dv+127)/128, MSEL/128);

    for (int l=0;l<NLv;l++) {
        k_rmsnorm<<<TOK/8, 256>>>(xp, attn_norm + (size_t)l*Dv, nullptr, hp);
        k_gemm_bf<<<gq, 128, SMEMG>>>(hp, wtp+OFF_QKV + (size_t)l*960*320, nullptr,
                                      nullptr, nullptr, nullptr, TOK, 3*Dv, Dv, 4);
        k_attn_tc<<<dim3(Sv/64, NHv, Bv), 128, SMEMA>>>();
        k_gemm_bf<<<g320, 128, SMEMG>>>(attp, wtp+OFF_WO + (size_t)l*320*320, xp,
                                        xp, nullptr, nullptr, TOK, Dv, Dv, 1);
        k_router<<<TOK/8, 256>>>(router + (size_t)l*Dv);
        k_topk<<<dim3(Bv, Sv/256), 256>>>();
        k_rmsnorm_sel<<<MSEL/8, 256>>>(mlp_norm + (size_t)l*Dv);
        k_gemm_gu<<<gffs, 256, SMEMGU>>>(hp, wtp+OFF_GATE + (size_t)l*FFv*320,
                                         wtp+OFF_UP + (size_t)l*FFv*320, g2p,
                                         MSEL, FFv, Dv);
        k_gemm_bf<<<g320s, 128, SMEMG>>>(g2p, wtp+OFF_DOWN + (size_t)l*320*FFv, xp,
                                         xp, wselp, selp, MSEL, Dv, FFv, 2);
    }
    k_rmsnorm<<<TOK/8, 256>>>(xp, final_norm, out, nullptr);
}

// round 16
// speedup vs baseline: 1.2626x; 1.0652x over previous
#include <cuda_runtime.h>
#include <cuda_bf16.h>
#include <math.h>

#define Bv 8
#define Sv 2048
#define Dv 320
#define NHv 5
#define HDv 64
#define FFv 864
#define NLv 6
#define NLOOPSv 8
#define TOK (Bv*Sv)
#define KSEL 1638
#define MPAD 1664
#define MSEL (Bv*MPAD)   // 13312

// ---------------- scratch ----------------
__device__ float g_x[TOK*Dv];
__device__ __nv_bfloat16 g_h[TOK*Dv];
__device__ float g_q[Bv*NHv*Sv*HDv];      // tf32 [B][H][S][HD]
__device__ float g_k[Bv*NHv*Sv*HDv];      // tf32 [B][H][S][HD]
__device__ __nv_bfloat16 g_v[Bv*NHv*Sv*HDv]; // bf16 TRANSPOSED [B][H][HD][S]
__device__ __nv_bfloat16 g_att[TOK*Dv];
__device__ float g_probs[TOK];
__device__ int   g_sel[MSEL];
__device__ float g_wselc[MSEL];
__device__ __nv_bfloat16 g_g2[TOK*FFv];
__device__ float2 g_rope[Sv*32];

#define OFF_QKV  0
#define OFF_WO   1843200
#define OFF_GATE 2457600
#define OFF_UP   4116480
#define OFF_DOWN 5775360
#define TOTW     7434240
__device__ __nv_bfloat16 g_wt[TOTW];

__device__ __forceinline__ float to_tf32(float x){
    unsigned u; asm("cvt.rna.tf32.f32 %0, %1;" : "=r"(u) : "f"(x));
    return __uint_as_float(u);
}
__device__ __forceinline__ unsigned fbits(float x){ return __float_as_uint(x); }
__device__ __forceinline__ unsigned packbf(float lo, float hi){
    __nv_bfloat162 t = __floats2bfloat162_rn(lo, hi);
    return *(unsigned*)&t;
}

#define MMA_TF32(acc, A0,A1,A2,A3, B0,B1)                                   \
    asm volatile(                                                           \
        "mma.sync.aligned.m16n8k8.row.col.f32.tf32.tf32.f32 "               \
        "{%0,%1,%2,%3},{%4,%5,%6,%7},{%8,%9},{%0,%1,%2,%3};\n"              \
        : "+f"(acc[0]),"+f"(acc[1]),"+f"(acc[2]),"+f"(acc[3])               \
        : "r"(A0),"r"(A1),"r"(A2),"r"(A3),"r"(B0),"r"(B1))

#define MMA_BF16(acc, A0,A1,A2,A3, B0,B1)                                   \
    asm volatile(                                                           \
        "mma.sync.aligned.m16n8k16.row.col.f32.bf16.bf16.f32 "              \
        "{%0,%1,%2,%3},{%4,%5,%6,%7},{%8,%9},{%0,%1,%2,%3};\n"              \
        : "+f"(acc[0]),"+f"(acc[1]),"+f"(acc[2]),"+f"(acc[3])               \
        : "r"(A0),"r"(A1),"r"(A2),"r"(A3),"r"(B0),"r"(B1))

#define LDSM4(r0,r1,r2,r3, addr)                                            \
    asm volatile("ldmatrix.sync.aligned.m8n8.x4.shared.b16 {%0,%1,%2,%3}, [%4];" \
        : "=r"(r0),"=r"(r1),"=r"(r2),"=r"(r3) : "r"(addr))

#define CPA(dst, src) asm volatile("cp.async.cg.shared.global [%0], [%1], 16;\n" :: "r"(dst), "l"(src))
#define CPAZ(dst, src, sz) asm volatile("cp.async.cg.shared.global [%0], [%1], 16, %2;\n" :: "r"(dst), "l"(src), "r"(sz))
#define CPCOMMIT() asm volatile("cp.async.commit_group;\n")
#define CPWAIT1() asm volatile("cp.async.wait_group 1;\n")

// ---------------- merged weight conversion ----------------
__global__ void k_cvt5(const float* __restrict__ a0, const float* __restrict__ a1,
                       const float* __restrict__ a2, const float* __restrict__ a3,
                       const float* __restrict__ a4){
    int i = blockIdx.x*256 + threadIdx.x;
    if (i >= TOTW) return;
    const float* src; int off;
    if (i < OFF_WO)        { src=a0; off=i; }
    else if (i < OFF_GATE) { src=a1; off=i-OFF_WO; }
    else if (i < OFF_UP)   { src=a2; off=i-OFF_GATE; }
    else if (i < OFF_DOWN) { src=a3; off=i-OFF_UP; }
    else                   { src=a4; off=i-OFF_DOWN; }
    g_wt[i] = __float2bfloat16(src[off]);
}

__global__ void k_ropetab(){
    int idx = blockIdx.x*256 + threadIdx.x;
    if (idx >= Sv*32) return;
    int s = idx >> 5, i2 = idx & 31;
    float freq = expf(-(float)(2*i2) * (9.210340371976184f/64.0f));
    float ang = (float)s * freq;
    float sn, cs; sincosf(ang, &sn, &cs);
    g_rope[idx] = make_float2(cs, sn);
}

__global__ void k_embed(const int* __restrict__ ids, const int* __restrict__ iter,
                        const float* __restrict__ emb, const float* __restrict__ iter_emb) {
    int idx = blockIdx.x*256 + threadIdx.x;
    if (idx >= TOK*Dv) return;
    int t = idx / Dv, d = idx - t*Dv;
    float v = emb[(size_t)ids[t]*Dv + d];
    int it = iter[0];
    if (it < NLOOPSv) v += iter_emb[it*Dv + d];
    g_x[idx] = v;
}

__global__ void k_clearpad(){
    int i = threadIdx.x;
    if (i < Bv*(MPAD-KSEL)){
        int b = i/(MPAD-KSEL), j = i%(MPAD-KSEL);
        g_sel[b*MPAD + KSEL + j] = -1;
        g_wselc[b*MPAD + KSEL + j] = 0.f;
    }
}

// ---------------- rmsnorm (dense) ----------------
__global__ void k_rmsnorm(const float* __restrict__ in, const float* __restrict__ w,
                          float* __restrict__ outf, __nv_bfloat16* __restrict__ outb) {
    int gw = (blockIdx.x*256 + threadIdx.x) >> 5;
    int lane = threadIdx.x & 31;
    if (gw >= TOK) return;
    const float* xr = in + (size_t)gw*Dv;
    float v[10]; float ss = 0.f;
    #pragma unroll
    for (int i=0;i<10;i++){ v[i] = xr[lane+32*i]; ss = fmaf(v[i],v[i],ss); }
    #pragma unroll
    for (int o=16;o;o>>=1) ss += __shfl_xor_sync(0xffffffffu, ss, o);
    float inv = rsqrtf(ss*(1.f/Dv) + 1e-6f);
    if (outb){
        __nv_bfloat16* orow = outb + (size_t)gw*Dv;
        #pragma unroll
        for (int i=0;i<10;i++) orow[lane+32*i] = __float2bfloat16(w[lane+32*i]*v[i]*inv);
    } else {
        float* orow = outf + (size_t)gw*Dv;
        #pragma unroll
        for (int i=0;i<10;i++) orow[lane+32*i] = w[lane+32*i]*v[i]*inv;
    }
}

// ---------------- rmsnorm over selected rows -> bf16 h ----------------
__global__ void k_rmsnorm_sel(const float* __restrict__ w) {
    int gw = (blockIdx.x*256 + threadIdx.x) >> 5;
    int lane = threadIdx.x & 31;
    if (gw >= MSEL) return;
    int tok = g_sel[gw];
    __nv_bfloat16* orow = g_h + (size_t)gw*Dv;
    if (tok < 0){
        #pragma unroll
        for (int i=0;i<10;i++) orow[lane+32*i] = __float2bfloat16(0.f);
        return;
    }
    const float* xr = g_x + (size_t)tok*Dv;
    float v[10]; float ss = 0.f;
    #pragma unroll
    for (int i=0;i<10;i++){ v[i] = xr[lane+32*i]; ss = fmaf(v[i],v[i],ss); }
    #pragma unroll
    for (int o=16;o;o>>=1) ss += __shfl_xor_sync(0xffffffffu, ss, o);
    float inv = rsqrtf(ss*(1.f/Dv) + 1e-6f);
    #pragma unroll
    for (int i=0;i<10;i++)
        orow[lane+32*i] = __float2bfloat16(w[lane+32*i]*v[i]*inv);
}

// ---------------- bf16 GEMM (128 thr, warp 64x64, ldmatrix, 3-stage cp.async) ----------------
// ep: 0 plain, 1 residual add, 2 MoE scatter add, 4 QKV+RoPE+Vtr
#define LDH 40
__global__ __launch_bounds__(128) void k_gemm_bf(
    const __nv_bfloat16* __restrict__ A, const __nv_bfloat16* __restrict__ W, void* Cv,
    const float* __restrict__ aux, const float* __restrict__ rowscale,
    const int* __restrict__ sel,
    int M, int N, int K, int ep)
{
    extern __shared__ __nv_bfloat16 smh[];
    const int SA = 128*LDH;
    unsigned base = (unsigned)__cvta_generic_to_shared(smh);
    unsigned Asb[3] = { base, base + (unsigned)(2*SA)*2u, base + (unsigned)(4*SA)*2u };
    unsigned Wsb[3] = { base + (unsigned)SA*2u, base + (unsigned)(3*SA)*2u, base + (unsigned)(5*SA)*2u };

    int tid = threadIdx.x;
    int lane = tid & 31, warp = tid >> 5;
    int wm = warp >> 1, wn = warp & 1;
    int m0 = blockIdx.y*128, n0 = blockIdx.x*128;

    int lrow = tid >> 2;
    int ck  = tid & 3;
    const __nv_bfloat16* Ag = A + (size_t)(m0 + lrow)*K + ck*8;
    int wr0 = n0 + lrow;

    float acc[4][8][4];
    #pragma unroll
    for (int i=0;i<4;i++)
        #pragma unroll
        for (int j=0;j<8;j++)
            #pragma unroll
            for (int c=0;c<4;c++) acc[i][j][c]=0.f;

    int nkb = K >> 5;

    #define LOADTILEB(st, k0) do {                                                \
        _Pragma("unroll")                                                         \
        for (int i=0;i<4;i++){                                                    \
            int r = lrow + 32*i;                                                  \
            unsigned d = Asb[st] + (unsigned)((r*LDH + ck*8)*2);                  \
            CPA(d, Ag + (size_t)(32*i)*K + (k0));                                 \
        }                                                                         \
        _Pragma("unroll")                                                         \
        for (int i=0;i<4;i++){                                                    \
            int r = lrow + 32*i;                                                  \
            int wr = wr0 + 32*i;                                                  \
            unsigned sz = (wr < N) ? 16u : 0u;                                    \
            const __nv_bfloat16* src = W + (size_t)(wr < N ? wr : 0)*K + (k0) + ck*8; \
            unsigned d = Wsb[st] + (unsigned)((r*LDH + ck*8)*2);                  \
            CPAZ(d, src, sz);                                                     \
        }                                                                         \
    } while(0)

    LOADTILEB(0, 0);
    CPCOMMIT();
    if (nkb > 1) LOADTILEB(1, 32);
    CPCOMMIT();

    int lr = lane >> 2, lc = lane & 3;
    int arow_l = lane & 15, achk_l = (lane >> 4)*8;
    int brow_l = ((lane >> 4) << 3) + (lane & 7), bchk_l = ((lane >> 3) & 1)*8;
    int st = 0;
    for (int kb=0; kb<nkb; kb++){
        CPWAIT1();
        __syncthreads();
        if (kb+2 < nkb){
            int st2 = (st+2 >= 3) ? st-1 : st+2;
            LOADTILEB(st2, (kb+2)*32);
        }
        CPCOMMIT();

        #pragma unroll
        for (int ks=0; ks<2; ks++){
            unsigned a[4][4], b[8][2];
            #pragma unroll
            for (int mf=0; mf<4; mf++){
                unsigned ad = Asb[st] +
                    (unsigned)(((wm*64 + mf*16 + arow_l)*LDH + ks*16 + achk_l)*2);
                LDSM4(a[mf][0], a[mf][1], a[mf][2], a[mf][3], ad);
            }
            #pragma unroll
            for (int np=0; np<4; np++){
                unsigned bd = Wsb[st] +
                    (unsigned)(((wn*64 + np*16 + brow_l)*LDH + ks*16 + bchk_l)*2);
                LDSM4(b[2*np][0], b[2*np][1], b[2*np+1][0], b[2*np+1][1], bd);
            }
            #pragma unroll
            for (int mf=0; mf<4; mf++)
                #pragma unroll
                for (int nf=0; nf<8; nf++)
                    MMA_BF16(acc[mf][nf], a[mf][0],a[mf][1],a[mf][2],a[mf][3],
                             b[nf][0], b[nf][1]);
        }
        st = (st+1 >= 3) ? 0 : st+1;
    }

    if (ep == 4){
        // smem is dead after the mainloop; barrier BEFORE any early-out.
        __syncthreads();
        int nb = n0 + wn*64;
        if (nb < N){
            int type = nb / 320;
            int h = (nb % 320) >> 6;
            if (type == 2){
                // stage V warp tile (64 d x 64 s) in smem, write coalesced uint4 rows
                __nv_bfloat16* stg = smh + warp*64*72;
                #pragma unroll
                for (int mf=0; mf<4; mf++)
                    #pragma unroll
                    for (int c=0;c<4;c++){
                        int ml = mf*16 + lr + ((c>=2)?8:0);
                        #pragma unroll
                        for (int nf=0;nf<8;nf++){
                            int d = nf*8 + lc*2 + (c&1);
                            stg[d*72 + ml] = __float2bfloat16(acc[mf][nf][c]);
                        }
                    }
                __syncwarp();
                int m0w = m0 + wm*64;
                int s0 = m0w & (Sv-1), bb = m0w >> 11;
                __nv_bfloat16* dst = g_v + (((size_t)bb*NHv+h)*HDv)*Sv + s0;
                #pragma unroll
                for (int i=0;i<16;i++){
                    int chunk = lane + i*32;
                    int d = chunk >> 3, cc = chunk & 7;
                    *(uint4*)(dst + (size_t)d*Sv + cc*8) = *(uint4*)(stg + d*72 + cc*8);
                }
            } else {
                float* dstqk = (type==0) ? g_q : g_k;
                #pragma unroll
                for (int mf=0; mf<4; mf++)
                    #pragma unroll
                    for (int cp=0;cp<2;cp++){
                        int m = m0 + wm*64 + mf*16 + lr + cp*8;
                        int s = m & (Sv-1), bb = m >> 11;
                        size_t o = (((size_t)bb*NHv+h)*Sv + s)*HDv;
                        #pragma unroll
                        for (int nf=0;nf<4;nf++){
                            int i2 = nf*8 + lc*2;
                            float4 rt = *(const float4*)&g_rope[(s<<5)+i2];
                            float vlo0 = acc[mf][nf][cp*2],   vlo1 = acc[mf][nf][cp*2+1];
                            float vhi0 = acc[mf][nf+4][cp*2], vhi1 = acc[mf][nf+4][cp*2+1];
                            float2 lo, hi;
                            lo.x = to_tf32(vlo0*rt.x - vhi0*rt.y);
                            lo.y = to_tf32(vlo1*rt.z - vhi1*rt.w);
                            hi.x = to_tf32(vhi0*rt.x + vlo0*rt.y);
                            hi.y = to_tf32(vhi1*rt.z + vlo1*rt.w);
                            *(float2*)(dstqk + o + i2)      = lo;
                            *(float2*)(dstqk + o + i2 + 32) = hi;
                        }
                    }
            }
        }
        return;
    }

    #pragma unroll
    for (int mf=0; mf<4; mf++){
        #pragma unroll
        for (int nf=0; nf<8; nf++){
            int mbase = m0 + wm*64 + mf*16 + lr;
            int nbase = n0 + wn*64 + nf*8 + lc*2;
            #pragma unroll
            for (int c=0;c<4;c++){
                int m = mbase + (c>=2 ? 8 : 0);
                int n = nbase + (c&1);
                if (n < N){
                    float v = acc[mf][nf][c];
                    if (ep==2){
                        int tok = sel[m];
                        if (tok >= 0){
                            size_t o = (size_t)tok*N + n;
                            ((float*)Cv)[o] = aux[o] + rowscale[m]*v;
                        }
                    } else {
                        size_t o = (size_t)m*N + n;
                        if (ep==0) ((float*)Cv)[o] = v;
                        else ((float*)Cv)[o] = aux[o] + v;
                    }
                }
            }
        }
    }
}

// ---------------- fused gate+up+swiglu GEMM (256 thr, 3-stage) ----------------
__global__ __launch_bounds__(256) void k_gemm_gu(
    const __nv_bfloat16* __restrict__ A, const __nv_bfloat16* __restrict__ Wg,
    const __nv_bfloat16* __restrict__ Wu, __nv_bfloat16* __restrict__ C,
    int M, int N, int K)
{
    extern __shared__ __nv_bfloat16 smh[];
    const int SA = 128*LDH;
    unsigned base = (unsigned)__cvta_generic_to_shared(smh);
    unsigned Asb[3] = { base,                      base + (unsigned)(3*SA)*2u, base + (unsigned)(6*SA)*2u };
    unsigned Gsb[3] = { base + (unsigned)SA*2u,    base + (unsigned)(4*SA)*2u, base + (unsigned)(7*SA)*2u };
    unsigned Usb[3] = { base + (unsigned)(2*SA)*2u,base + (unsigned)(5*SA)*2u, base + (unsigned)(8*SA)*2u };

    int tid = threadIdx.x;
    int lane = tid & 31, warp = tid >> 5;
    int wm = warp >> 2, wn2 = warp & 3;
    int m0 = blockIdx.y*128, n0 = blockIdx.x*128;

    int lrow = tid >> 2;
    int ck  = tid & 3;
    const __nv_bfloat16* Ag = A + (size_t)(m0 + lrow)*K + ck*8;
    int wr0 = n0 + lrow;

    float ag[4][4][4], au[4][4][4];
    #pragma unroll
    for (int i=0;i<4;i++)
        #pragma unroll
        for (int j=0;j<4;j++)
            #pragma unroll
            for (int c=0;c<4;c++){ ag[i][j][c]=0.f; au[i][j][c]=0.f; }

    int nkb = K >> 5;

    #define LOADTILEGU(st, k0) do {                                               \
        _Pragma("unroll")                                                         \
        for (int i=0;i<2;i++){                                                    \
            int r = lrow + 64*i;                                                  \
            unsigned d = Asb[st] + (unsigned)((r*LDH + ck*8)*2);                  \
            CPA(d, Ag + (size_t)(64*i)*K + (k0));                                 \
        }                                                                         \
        _Pragma("unroll")                                                         \
        for (int i=0;i<2;i++){                                                    \
            int r = lrow + 64*i;                                                  \
            int wr = wr0 + 64*i;                                                  \
            unsigned sz = (wr < N) ? 16u : 0u;                                    \
            size_t so = (size_t)(wr < N ? wr : 0)*K + (k0) + ck*8;                \
            unsigned dg = Gsb[st] + (unsigned)((r*LDH + ck*8)*2);                  \
            CPAZ(dg, Wg + so, sz);                                                \
            unsigned du = Usb[st] + (unsigned)((r*LDH + ck*8)*2);                  \
            CPAZ(du, Wu + so, sz);                                                \
        }                                                                         \
    } while(0)

    LOADTILEGU(0, 0);
    CPCOMMIT();
    if (nkb > 1) LOADTILEGU(1, 32);
    CPCOMMIT();

    int lr = lane >> 2, lc = lane & 3;
    int arow_l = lane & 15, achk_l = (lane >> 4)*8;
    int brow_l = ((lane >> 4) << 3) + (lane & 7), bchk_l = ((lane >> 3) & 1)*8;
    int st = 0;
    for (int kb=0; kb<nkb; kb++){
        CPWAIT1();
        __syncthreads();
        if (kb+2 < nkb){
            int st2 = (st+2 >= 3) ? st-1 : st+2;
            LOADTILEGU(st2, (kb+2)*32);
        }
        CPCOMMIT();

        #pragma unroll
        for (int ks=0; ks<2; ks++){
            unsigned a[4][4], bg[4][2], bu[4][2];
            #pragma unroll
            for (int mf=0; mf<4; mf++){
                unsigned ad = Asb[st] +
                    (unsigned)(((wm*64 + mf*16 + arow_l)*LDH + ks*16 + achk_l)*2);
                LDSM4(a[mf][0], a[mf][1], a[mf][2], a[mf][3], ad);
            }
            #pragma unroll
            for (int np=0; np<2; np++){
                unsigned row = (unsigned)(wn2*32 + np*16 + brow_l);
                unsigned off = (unsigned)((row*LDH + ks*16 + bchk_l)*2);
                LDSM4(bg[2*np][0], bg[2*np][1], bg[2*np+1][0], bg[2*np+1][1], Gsb[st] + off);
                LDSM4(bu[2*np][0], bu[2*np][1], bu[2*np+1][0], bu[2*np+1][1], Usb[st] + off);
            }
            #pragma unroll
            for (int mf=0; mf<4; mf++)
                #pragma unroll
                for (int nf=0; nf<4; nf++){
                    MMA_BF16(ag[mf][nf], a[mf][0],a[mf][1],a[mf][2],a[mf][3],
                             bg[nf][0], bg[nf][1]);
                    MMA_BF16(au[mf][nf], a[mf][0],a[mf][1],a[mf][2],a[mf][3],
                             bu[nf][0], bu[nf][1]);
                }
        }
        st = (st+1 >= 3) ? 0 : st+1;
    }

    #pragma unroll
    for (int mf=0; mf<4; mf++){
        #pragma unroll
        for (int nf=0; nf<4; nf++){
            int mbase = m0 + wm*64 + mf*16 + lr;
            int nbase = n0 + wn2*32 + nf*8 + lc*2;
            #pragma unroll
            for (int c=0;c<4;c+=2){
                int m = mbase + (c>=2 ? 8 : 0);
                if (nbase < N){
                    float gg0 = ag[mf][nf][c],   uu0 = au[mf][nf][c];
                    float gg1 = ag[mf][nf][c+1], uu1 = au[mf][nf][c+1];
                    unsigned pk = packbf(gg0*uu0/(1.f+expf(-gg0)),
                                         gg1*uu1/(1.f+expf(-gg1)));
                    *(unsigned*)(C + (size_t)m*N + nbase) = pk;
                }
            }
        }
    }
}

// ---------------- flash attention: tf32 QK^T + bf16 PV (P in registers) ----------------
#define APAD 68
#define VPAD 72
__global__ __launch_bounds__(128) void k_attn_tc() {
    extern __shared__ char smraw[];
    float* Qs = (float*)smraw;                            // [64][68] fp32
    float* Ks = Qs + 64*APAD;                             // [64][68] fp32
    __nv_bfloat16* Vt = (__nv_bfloat16*)(Ks + 64*APAD);   // [64][72] bf16 dim-major
    int qt = gridDim.x - 1 - blockIdx.x;   // heavy tiles first
    int h = blockIdx.y, b = blockIdx.z;
    int tid = threadIdx.x, lane = tid & 31, warp = tid >> 5;
    int lr = lane >> 2, lc = lane & 3;
    const size_t headoff = ((size_t)b*NHv + h)*(size_t)Sv*HDv;
    const float* Qg = g_q + headoff + (size_t)qt*64*HDv;
    const float* Kg0 = g_k + headoff;
    const __nv_bfloat16* Vg0 = g_v + headoff;   // [HD][S] bf16

    unsigned vtb = (unsigned)__cvta_generic_to_shared(Vt);
    int brow_l = ((lane >> 4) << 3) + (lane & 7), bchk_l = ((lane >> 3) & 1)*8;

    #pragma unroll
    for (int i=0;i<8;i++){
        int idx = (tid + i*128)*4;
        int row = idx >> 6, col = idx & 63;
        *(float4*)(Qs + row*APAD + col) = *(const float4*)(Qg + idx);
    }

    float o[8][4];
    #pragma unroll
    for (int nt=0;nt<8;nt++)
        #pragma unroll
        for (int c=0;c<4;c++) o[nt][c]=0.f;
    float mr0=-1e30f, mr1=-1e30f, ls0=0.f, ls1=0.f;
    int qrow = qt*64 + warp*16 + lr;

    for (int t0=0; t0<=qt; t0++){
        __syncthreads();
        const float* Kg = Kg0 + (size_t)t0*64*HDv;
        #pragma unroll
        for (int i=0;i<8;i++){
            int idx = (tid + i*128)*4;
            int row = idx >> 6, col = idx & 63;
            *(float4*)(Ks + row*APAD + col) = *(const float4*)(Kg + idx);
        }
        #pragma unroll
        for (int i=0;i<4;i++){
            int idx = (tid + i*128)*8;
            int row = idx >> 6, col = idx & 63;
            *(uint4*)(Vt + row*VPAD + col) = *(const uint4*)(Vg0 + (size_t)row*Sv + t0*64 + col);
        }
        __syncthreads();

        float sacc[8][4];
        #pragma unroll
        for (int nt=0;nt<8;nt++)
            #pragma unroll
            for (int c=0;c<4;c++) sacc[nt][c]=0.f;
        #pragma unroll
        for (int ks=0; ks<8; ks++){
            const float* ap = Qs + (warp*16 + lr)*APAD + ks*8 + lc;
            unsigned a0=fbits(ap[0]), a1=fbits(ap[8*APAD]),
                     a2=fbits(ap[4]), a3=fbits(ap[8*APAD+4]);
            #pragma unroll
            for (int nt=0; nt<8; nt++){
                const float* bp = Ks + (nt*8 + lr)*APAD + ks*8 + lc;
                MMA_TF32(sacc[nt], a0,a1,a2,a3, fbits(bp[0]), fbits(bp[4]));
            }
        }

        bool diag = (t0 == qt);
        float mt0=-1e30f, mt1=-1e30f;
        #pragma unroll
        for (int nt=0;nt<8;nt++){
            #pragma unroll
            for (int c=0;c<4;c++){
                float s = sacc[nt][c]*0.125f;
                if (diag){
                    int col = t0*64 + nt*8 + lc*2 + (c&1);
                    int row = qrow + ((c>=2)?8:0);
                    if (col > row) s = -1e30f;
                }
                sacc[nt][c] = s;
                if (c>=2) mt1 = fmaxf(mt1, s); else mt0 = fmaxf(mt0, s);
            }
        }
        mt0 = fmaxf(mt0, __shfl_xor_sync(0xffffffffu, mt0, 1));
        mt0 = fmaxf(mt0, __shfl_xor_sync(0xffffffffu, mt0, 2));
        mt1 = fmaxf(mt1, __shfl_xor_sync(0xffffffffu, mt1, 1));
        mt1 = fmaxf(mt1, __shfl_xor_sync(0xffffffffu, mt1, 2));
        float mn0 = fmaxf(mr0, mt0), mn1 = fmaxf(mr1, mt1);
        float sc0 = __expf(mr0 - mn0), sc1 = __expf(mr1 - mn1);
        ls0 *= sc0; ls1 *= sc1;
        #pragma unroll
        for (int nt=0;nt<8;nt++){
            o[nt][0]*=sc0; o[nt][1]*=sc0; o[nt][2]*=sc1; o[nt][3]*=sc1;
        }
        mr0 = mn0; mr1 = mn1;

        #pragma unroll
        for (int nt=0;nt<8;nt++){
            float p0 = __expf(sacc[nt][0] - mn0);
            float p1 = __expf(sacc[nt][1] - mn0);
            float p2 = __expf(sacc[nt][2] - mn1);
            float p3 = __expf(sacc[nt][3] - mn1);
            ls0 += p0 + p1; ls1 += p2 + p3;
            sacc[nt][0]=p0; sacc[nt][1]=p1; sacc[nt][2]=p2; sacc[nt][3]=p3;
        }

        #pragma unroll
        for (int ks=0; ks<4; ks++){
            unsigned a0 = packbf(sacc[2*ks][0],   sacc[2*ks][1]);
            unsigned a1 = packbf(sacc[2*ks][2],   sacc[2*ks][3]);
            unsigned a2 = packbf(sacc[2*ks+1][0], sacc[2*ks+1][1]);
            unsigned a3 = packbf(sacc[2*ks+1][2], sacc[2*ks+1][3]);
            unsigned bfr[8][2];
            #pragma unroll
            for (int np=0; np<4; np++){
                unsigned bd = vtb + (unsigned)(((np*16 + brow_l)*VPAD + ks*16 + bchk_l)*2);
                LDSM4(bfr[2*np][0], bfr[2*np][1], bfr[2*np+1][0], bfr[2*np+1][1], bd);
            }
            #pragma unroll
            for (int nt=0; nt<8; nt++)
                MMA_BF16(o[nt], a0,a1,a2,a3, bfr[nt][0], bfr[nt][1]);
        }
    }

    ls0 += __shfl_xor_sync(0xffffffffu, ls0, 1);
    ls0 += __shfl_xor_sync(0xffffffffu, ls0, 2);
    ls1 += __shfl_xor_sync(0xffffffffu, ls1, 1);
    ls1 += __shfl_xor_sync(0xffffffffu, ls1, 2);
    float inv0 = 1.f/ls0, inv1 = 1.f/ls1;
    int tok0 = b*Sv + qt*64 + warp*16 + lr;
    __nv_bfloat16* out0 = g_att + (size_t)tok0*Dv + h*HDv;
    __nv_bfloat16* out1 = out0 + 8*(size_t)Dv;
    #pragma unroll
    for (int nt=0;nt<8;nt++){
        int col = nt*8 + lc*2;
        *(unsigned*)(out0 + col) = packbf(o[nt][0]*inv0, o[nt][1]*inv0);
        *(unsigned*)(out1 + col) = packbf(o[nt][2]*inv1, o[nt][3]*inv1);
    }
}

// ---------------- router ----------------
__global__ void k_router(const float* __restrict__ rw) {
    int gw = (blockIdx.x*256 + threadIdx.x) >> 5;
    int lane = threadIdx.x & 31;
    if (gw >= TOK) return;
    const float* xr = g_x + (size_t)gw*Dv;
    float s = 0.f;
    #pragma unroll
    for (int i=0;i<10;i++) s = fmaf(xr[lane+32*i], rw[lane+32*i], s);
    #pragma unroll
    for (int o=16;o;o>>=1) s += __shfl_xor_sync(0xffffffffu, s, o);
    if (lane==0) g_probs[gw] = 1.f/(1.f+expf(-s));
}

// ---------------- exact top-k -> compact selection ----------------
__global__ __launch_bounds__(256) void k_topk() {
    __shared__ float p[Sv];
    int b = blockIdx.x, part = blockIdx.y;
    int tid = threadIdx.x;
    for (int i=tid;i<Sv;i+=256) p[i] = g_probs[b*Sv+i];
    __syncthreads();
    int i = part*256 + tid;
    float pi = p[i];
    int cnt = 0;
    #pragma unroll 8
    for (int j=0;j<Sv;j++) {
        float pj = p[j];
        cnt += (pj > pi) || (pj == pi && j < i);
    }
    if (cnt < KSEL){
        g_sel[b*MPAD + cnt] = b*Sv + i;
        g_wselc[b*MPAD + cnt] = pi;
    }
}

// ---------------- driver ----------------
extern "C" void kernel_launch(void* const* d_in, const int* in_sizes, int n_in,
                              void* d_out, int out_size) {
    const int*   ids        = (const int*)d_in[0];
    const int*   iter       = (const int*)d_in[1];
    const float* emb        = (const float*)d_in[2];
    const float* iter_emb   = (const float*)d_in[3];
    const float* attn_norm  = (const float*)d_in[4];
    const float* Wqkv       = (const float*)d_in[5];
    const float* wo         = (const float*)d_in[6];
    const float* router     = (const float*)d_in[7];
    const float* mlp_norm   = (const float*)d_in[8];
    const float* gatew      = (const float*)d_in[9];
    const float* upw        = (const float*)d_in[10];
    const float* downw      = (const float*)d_in[11];
    const float* final_norm = (const float*)d_in[12];
    float* out = (float*)d_out;

    float *xp,*wselp;
    __nv_bfloat16 *hp,*attp,*g2p,*wtp;
    int *selp;
    cudaGetSymbolAddress((void**)&xp,   g_x);
    cudaGetSymbolAddress((void**)&hp,   g_h);
    cudaGetSymbolAddress((void**)&attp, g_att);
    cudaGetSymbolAddress((void**)&g2p,  g_g2);
    cudaGetSymbolAddress((void**)&wselp,g_wselc);
    cudaGetSymbolAddress((void**)&selp, g_sel);
    cudaGetSymbolAddress((void**)&wtp,  g_wt);

    const int SMEMA = 2*64*APAD*4 + 64*VPAD*2;     // 44032
    const int SMEMG = 6*128*LDH*2;                 // 61440
    const int SMEMGU = 9*128*LDH*2;                // 92160
    cudaFuncSetAttribute(k_attn_tc, cudaFuncAttributeMaxDynamicSharedMemorySize, SMEMA);
    cudaFuncSetAttribute(k_gemm_bf, cudaFuncAttributeMaxDynamicSharedMemorySize, SMEMG);
    cudaFuncSetAttribute(k_gemm_gu, cudaFuncAttributeMaxDynamicSharedMemorySize, SMEMGU);

    k_ropetab<<<(Sv*32+255)/256, 256>>>();
    k_cvt5<<<(TOTW+255)/256, 256>>>(Wqkv, wo, gatew, upw, downw);
    k_embed<<<(TOK*Dv+255)/256, 256>>>(ids, iter, emb, iter_emb);
    k_clearpad<<<1, 256>>>();

    dim3 gq((3*Dv+127)/128, TOK/128);
    dim3 g320((Dv+127)/128, TOK/128);
    dim3 gffs((FFv+127)/128, MSEL/128);
    dim3 g320s((Dv+127)/128, MSEL/128);

    for (int l=0;l<NLv;l++) {
        k_rmsnorm<<<TOK/8, 256>>>(xp, attn_norm + (size_t)l*Dv, nullptr, hp);
        k_gemm_bf<<<gq, 128, SMEMG>>>(hp, wtp+OFF_QKV + (size_t)l*960*320, nullptr,
                                      nullptr, nullptr, nullptr, TOK, 3*Dv, Dv, 4);
        k_attn_tc<<<dim3(Sv/64, NHv, Bv), 128, SMEMA>>>();
        k_gemm_bf<<<g320, 128, SMEMG>>>(attp, wtp+OFF_WO + (size_t)l*320*320, xp,
                                        xp, nullptr, nullptr, TOK, Dv, Dv, 1);
        k_router<<<TOK/8, 256>>>(router + (size_t)l*Dv);
        k_topk<<<dim3(Bv, Sv/256), 256>>>();
        k_rmsnorm_sel<<<MSEL/8, 256>>>(mlp_norm + (size_t)l*Dv);
        k_gemm_gu<<<gffs, 256, SMEMGU>>>(hp, wtp+OFF_GATE + (size_t)l*FFv*320,
                                         wtp+OFF_UP + (size_t)l*FFv*320, g2p,
                                         MSEL, FFv, Dv);
        k_gemm_bf<<<g320s, 128, SMEMG>>>(g2p, wtp+OFF_DOWN + (size_t)l*320*FFv, xp,
                                         xp, wselp, selp, MSEL, Dv, FFv, 2);
    }
    k_rmsnorm<<<TOK/8, 256>>>(xp, final_norm, out, nullptr);
}